// round 14
// baseline (speedup 1.0000x reference)
#include <cuda_runtime.h>
#include <cuda_fp16.h>
#include <math.h>
#include <stdint.h>

#define TT   2048
#define HH   1024
#define NHQ  16
#define NKVH 4
#define HD   64
#define QKVD ((NHQ + 2*NKVH) * HD)   // 1536
#define NE   8
#define NI   2048
#define EPSV 1e-5f

typedef __half h16;

// ---------------- scratch (device globals; no allocations) ----------------
__device__ float g_qkv    [(size_t)TT * QKVD];
__device__ float g_resattn[(size_t)TT * HH];
__device__ float g_m      [(size_t)TT * HH];
__device__ int   g_cnt    [NE];
__device__ int   g_tok    [NE * TT];
__device__ float g_wt     [NE * TT];

__device__ __align__(16) h16 s_h    [(size_t)TT * HH];
__device__ __align__(16) h16 s_mh   [(size_t)TT * HH];
__device__ __align__(16) h16 s_attn [(size_t)TT * HH];
__device__ __align__(16) h16 s_silu [(size_t)TT * HH];
__device__ __align__(16) h16 s_qkvw [(size_t)QKVD * HH];
__device__ __align__(16) h16 s_ow   [(size_t)HH * HH];
__device__ __align__(16) h16 s_w13i [(size_t)2 * HH * HH];
__device__ __align__(16) h16 s_w2   [(size_t)HH * HH];
__device__ __align__(16) h16 s_wsi  [(size_t)NE * 2 * NI * HH];
__device__ __align__(16) h16 s_w2s  [(size_t)NE * HH * NI];
__device__ __align__(16) h16 s_act  [(size_t)NE * TT * NI];

// ---------------- helpers ----------------
__device__ __forceinline__ void mma16816(float* c, const uint32_t* a, const uint32_t* b) {
    asm volatile(
        "mma.sync.aligned.m16n8k16.row.col.f32.f16.f16.f32 "
        "{%0,%1,%2,%3}, {%4,%5,%6,%7}, {%8,%9}, {%0,%1,%2,%3};"
        : "+f"(c[0]), "+f"(c[1]), "+f"(c[2]), "+f"(c[3])
        : "r"(a[0]), "r"(a[1]), "r"(a[2]), "r"(a[3]), "r"(b[0]), "r"(b[1]));
}

__device__ __forceinline__ void ldsm4(uint32_t* r, uint32_t addr) {
    asm volatile("ldmatrix.sync.aligned.m8n8.x4.shared.b16 {%0,%1,%2,%3}, [%4];"
        : "=r"(r[0]), "=r"(r[1]), "=r"(r[2]), "=r"(r[3]) : "r"(addr));
}

__device__ __forceinline__ void cpasync16(uint32_t dst, const void* src) {
    asm volatile("cp.async.cg.shared.global [%0], [%1], 16;" :: "r"(dst), "l"(src));
}
__device__ __forceinline__ void cp_commit() {
    asm volatile("cp.async.commit_group;");
}
template<int N>
__device__ __forceinline__ void cp_wait() {
    asm volatile("cp.async.wait_group %0;" :: "n"(N));
}

// ---------------- utility kernels ----------------
__global__ void zero_cnt_kernel() {
    if (threadIdx.x < NE) g_cnt[threadIdx.x] = 0;
}

__global__ void copy_kernel(const float* __restrict__ src, float* __restrict__ dst,
                            long long n4) {
    long long i = (long long)blockIdx.x * 256 + threadIdx.x;
    long long stride = (long long)gridDim.x * 256;
    for (; i < n4; i += stride)
        ((float4*)dst)[i] = ((const float4*)src)[i];
}

__global__ void conv_kernel(const float* __restrict__ in, h16* __restrict__ out,
                            long long total16) {
    long long idx = (long long)blockIdx.x * 256 + threadIdx.x;
    long long stride = (long long)gridDim.x * 256;
    for (; idx < total16; idx += stride) {
        const float4* ip = (const float4*)&in[idx * 16];
        float4 v0 = ip[0], v1 = ip[1], v2 = ip[2], v3 = ip[3];
        __half2 h[8];
        h[0] = __floats2half2_rn(v0.x, v0.y); h[1] = __floats2half2_rn(v0.z, v0.w);
        h[2] = __floats2half2_rn(v1.x, v1.y); h[3] = __floats2half2_rn(v1.z, v1.w);
        h[4] = __floats2half2_rn(v2.x, v2.y); h[5] = __floats2half2_rn(v2.z, v2.w);
        h[6] = __floats2half2_rn(v3.x, v3.y); h[7] = __floats2half2_rn(v3.z, v3.w);
        *(uint4*)&out[idx * 16]     = *(uint4*)&h[0];
        *(uint4*)&out[idx * 16 + 8] = *(uint4*)&h[4];
    }
}

__global__ void conv_interleave_kernel(const float* __restrict__ in, h16* __restrict__ out,
                                       int K, int I, int groups) {
    long long idx = (long long)blockIdx.x * 256 + threadIdx.x;
    int K16 = K >> 4;
    long long per_group = (long long)2 * I * K16;
    long long total = (long long)groups * per_group;
    if (idx >= total) return;
    int g = (int)(idx / per_group);
    long long rem = idx % per_group;
    int r = (int)(rem / K16);
    int kq = (int)(rem % K16) * 16;
    int outr = (r < I) ? (2 * r) : (2 * (r - I) + 1);
    const float4* ip = (const float4*)&in[((size_t)g * 2 * I + r) * K + kq];
    float4 v0 = ip[0], v1 = ip[1], v2 = ip[2], v3 = ip[3];
    __half2 h[8];
    h[0] = __floats2half2_rn(v0.x, v0.y); h[1] = __floats2half2_rn(v0.z, v0.w);
    h[2] = __floats2half2_rn(v1.x, v1.y); h[3] = __floats2half2_rn(v1.z, v1.w);
    h[4] = __floats2half2_rn(v2.x, v2.y); h[5] = __floats2half2_rn(v2.z, v2.w);
    h[6] = __floats2half2_rn(v3.x, v3.y); h[7] = __floats2half2_rn(v3.z, v3.w);
    h16* o = out + ((size_t)g * 2 * I + outr) * K + kq;
    *(uint4*)&o[0] = *(uint4*)&h[0];
    *(uint4*)&o[8] = *(uint4*)&h[4];
}

__global__ void rmsnorm_h_kernel(const float* __restrict__ x,
                                 const float* __restrict__ w,
                                 h16* __restrict__ o) {
    int t = blockIdx.x;
    float4 xv = ((const float4*)(x + (size_t)t * HH))[threadIdx.x];
    float s = xv.x * xv.x + xv.y * xv.y + xv.z * xv.z + xv.w * xv.w;
    __shared__ float red[256];
    red[threadIdx.x] = s;
    __syncthreads();
    for (int k = 128; k > 0; k >>= 1) {
        if (threadIdx.x < k) red[threadIdx.x] += red[threadIdx.x + k];
        __syncthreads();
    }
    float rs = rsqrtf(red[0] / (float)HH + EPSV);
    float4 wv = ((const float4*)w)[threadIdx.x];
    h16* op = o + (size_t)t * HH + threadIdx.x * 4;
    *(__half2*)&op[0] = __floats2half2_rn(xv.x * rs * wv.x, xv.y * rs * wv.y);
    *(__half2*)&op[2] = __floats2half2_rn(xv.z * rs * wv.z, xv.w * rs * wv.w);
}

__global__ void rmsnorm_fh_kernel(const float* __restrict__ x,
                                  const float* __restrict__ w,
                                  float* __restrict__ of, h16* __restrict__ oh) {
    int t = blockIdx.x;
    float4 xv = ((const float4*)(x + (size_t)t * HH))[threadIdx.x];
    float s = xv.x * xv.x + xv.y * xv.y + xv.z * xv.z + xv.w * xv.w;
    __shared__ float red[256];
    red[threadIdx.x] = s;
    __syncthreads();
    for (int k = 128; k > 0; k >>= 1) {
        if (threadIdx.x < k) red[threadIdx.x] += red[threadIdx.x + k];
        __syncthreads();
    }
    float rs = rsqrtf(red[0] / (float)HH + EPSV);
    float4 wv = ((const float4*)w)[threadIdx.x];
    float4 ov = make_float4(xv.x * rs * wv.x, xv.y * rs * wv.y, xv.z * rs * wv.z, xv.w * rs * wv.w);
    ((float4*)(of + (size_t)t * HH))[threadIdx.x] = ov;
    h16* op = oh + (size_t)t * HH + threadIdx.x * 4;
    *(__half2*)&op[0] = __floats2half2_rn(ov.x, ov.y);
    *(__half2*)&op[2] = __floats2half2_rn(ov.z, ov.w);
}

__global__ void rope_kernel(float* __restrict__ qkv, const int* __restrict__ positions) {
    int idx = blockIdx.x * 256 + threadIdx.x;
    if (idx >= TT * (NHQ + NKVH) * 32) return;
    int t = idx / ((NHQ + NKVH) * 32);
    int rem = idx % ((NHQ + NKVH) * 32);
    int h = rem >> 5;
    int d = rem & 31;
    int off = (h < NHQ) ? h * HD : NHQ * HD + (h - NHQ) * HD;
    float* p = qkv + (size_t)t * QKVD + off;
    float x1 = p[d];
    float x2 = p[d + 32];
    float pos = (float)positions[t];
    float invf = __expf(-0.2878231366f * (float)d);   // ln(10000)/32
    float fr = pos * invf;
    float c, s;
    __sincosf(fr, &s, &c);
    p[d]      = x1 * c - x2 * s;
    p[d + 32] = x2 * c + x1 * s;
}

// ---------------- flash attention: BR=128 x BC=64, register softmax, f16x2 ex2 ----------------
#define ATT_SMEM ((128 + 64 + 64) * 72 * 2)

__global__ __launch_bounds__(256) void attn_mma_kernel(
    const float* __restrict__ qkv, h16* __restrict__ outH) {
    extern __shared__ char smraw[];
    h16* Qh = (h16*)smraw;
    h16* Kh = Qh + 128 * 72;
    h16* Vh = Kh + 64 * 72;

    int qblk = gridDim.x - 1 - blockIdx.x;
    int h = blockIdx.y;
    int kvh = h >> 2;
    int tid = threadIdx.x, lane = tid & 31, w = tid >> 5;
    int r = lane >> 2, tq = (lane & 3) * 2;
    int q0 = qblk * 128 + w * 16 + r;

    for (int i = tid; i < 128 * 16; i += 256) {
        int row = i >> 4, c = (i & 15) << 2;
        float4 v = *(const float4*)&qkv[(size_t)(qblk * 128 + row) * QKVD + h * HD + c];
        h16* qp = Qh + row * 72 + c;
        *(__half2*)&qp[0] = __floats2half2_rn(v.x, v.y);
        *(__half2*)&qp[2] = __floats2half2_rn(v.z, v.w);
    }

    const float c2 = 0.18033688011112042f;
    float m0 = -1e30f, m1 = -1e30f, l0 = 0.f, l1 = 0.f;
    float oacc[8][4] = {};

    int ktmax = qblk * 2 + 1;
    for (int kt = 0; kt <= ktmax; kt++) {
        __syncthreads();
        for (int i = tid; i < 64 * 16; i += 256) {
            int row = i >> 4, c = (i & 15) << 2;
            size_t base = (size_t)(kt * 64 + row) * QKVD + NHQ * HD + kvh * HD;
            float4 kv = *(const float4*)&qkv[base + c];
            h16* kp = Kh + row * 72 + c;
            *(__half2*)&kp[0] = __floats2half2_rn(kv.x, kv.y);
            *(__half2*)&kp[2] = __floats2half2_rn(kv.z, kv.w);
            float4 vv = *(const float4*)&qkv[base + NKVH * HD + c];
            Vh[(c + 0) * 72 + row] = __float2half(vv.x);
            Vh[(c + 1) * 72 + row] = __float2half(vv.y);
            Vh[(c + 2) * 72 + row] = __float2half(vv.z);
            Vh[(c + 3) * 72 + row] = __float2half(vv.w);
        }
        __syncthreads();

        float sacc[8][4] = {};
        #pragma unroll
        for (int kb = 0; kb < 4; kb++) {
            int kbo = kb * 16;
            uint32_t af[4];
            const h16* qb = Qh + (w * 16 + r) * 72 + kbo + tq;
            af[0] = *(const uint32_t*)qb;
            af[1] = *(const uint32_t*)(qb + 8 * 72);
            af[2] = *(const uint32_t*)(qb + 8);
            af[3] = *(const uint32_t*)(qb + 8 * 72 + 8);
            #pragma unroll
            for (int nn = 0; nn < 8; nn++) {
                uint32_t bf[2];
                const h16* kbp = Kh + (nn * 8 + r) * 72 + kbo + tq;
                bf[0] = *(const uint32_t*)kbp;
                bf[1] = *(const uint32_t*)(kbp + 8);
                mma16816(sacc[nn], af, bf);
            }
        }

        int colb = kt * 64;
        if ((colb + 63) > q0) {
            #pragma unroll
            for (int nn = 0; nn < 8; nn++) {
                int c0 = colb + nn * 8 + tq;
                sacc[nn][0] = (c0     <= q0    ) ? sacc[nn][0] * c2 : -1e30f;
                sacc[nn][1] = (c0 + 1 <= q0    ) ? sacc[nn][1] * c2 : -1e30f;
                sacc[nn][2] = (c0     <= q0 + 8) ? sacc[nn][2] * c2 : -1e30f;
                sacc[nn][3] = (c0 + 1 <= q0 + 8) ? sacc[nn][3] * c2 : -1e30f;
            }
        } else {
            #pragma unroll
            for (int nn = 0; nn < 8; nn++) {
                sacc[nn][0] *= c2; sacc[nn][1] *= c2;
                sacc[nn][2] *= c2; sacc[nn][3] *= c2;
            }
        }

        float mt0 = -1e30f, mt1 = -1e30f;
        #pragma unroll
        for (int nn = 0; nn < 8; nn++) {
            mt0 = fmaxf(mt0, fmaxf(sacc[nn][0], sacc[nn][1]));
            mt1 = fmaxf(mt1, fmaxf(sacc[nn][2], sacc[nn][3]));
        }
        mt0 = fmaxf(mt0, __shfl_xor_sync(0xffffffffu, mt0, 1));
        mt0 = fmaxf(mt0, __shfl_xor_sync(0xffffffffu, mt0, 2));
        mt1 = fmaxf(mt1, __shfl_xor_sync(0xffffffffu, mt1, 1));
        mt1 = fmaxf(mt1, __shfl_xor_sync(0xffffffffu, mt1, 2));
        float nm0 = fmaxf(m0, mt0), nm1 = fmaxf(m1, mt1);
        float corr0 = exp2f(m0 - nm0), corr1 = exp2f(m1 - nm1);
        m0 = nm0; m1 = nm1;

        uint32_t pa[8], pb[8];
        float s0 = 0.f, s1 = 0.f;
        #pragma unroll
        for (int nn = 0; nn < 8; nn++) {
            __half2 ta = __floats2half2_rn(sacc[nn][0] - nm0, sacc[nn][1] - nm0);
            __half2 tb = __floats2half2_rn(sacc[nn][2] - nm1, sacc[nn][3] - nm1);
            uint32_t ua, ub;
            asm("ex2.approx.f16x2 %0, %1;" : "=r"(ua) : "r"(*(uint32_t*)&ta));
            asm("ex2.approx.f16x2 %0, %1;" : "=r"(ub) : "r"(*(uint32_t*)&tb));
            pa[nn] = ua; pb[nn] = ub;
            float2 fa = __half22float2(*(__half2*)&ua);
            float2 fb = __half22float2(*(__half2*)&ub);
            s0 += fa.x + fa.y; s1 += fb.x + fb.y;
        }
        s0 += __shfl_xor_sync(0xffffffffu, s0, 1);
        s0 += __shfl_xor_sync(0xffffffffu, s0, 2);
        s1 += __shfl_xor_sync(0xffffffffu, s1, 1);
        s1 += __shfl_xor_sync(0xffffffffu, s1, 2);
        l0 = l0 * corr0 + s0;
        l1 = l1 * corr1 + s1;

        #pragma unroll
        for (int nn = 0; nn < 8; nn++) {
            oacc[nn][0] *= corr0; oacc[nn][1] *= corr0;
            oacc[nn][2] *= corr1; oacc[nn][3] *= corr1;
        }
        #pragma unroll
        for (int kb = 0; kb < 4; kb++) {
            uint32_t af[4] = { pa[2 * kb], pb[2 * kb], pa[2 * kb + 1], pb[2 * kb + 1] };
            int kbo = kb * 16;
            #pragma unroll
            for (int nn = 0; nn < 8; nn++) {
                uint32_t bf[2];
                const h16* vbp = Vh + (nn * 8 + r) * 72 + kbo + tq;
                bf[0] = *(const uint32_t*)vbp;
                bf[1] = *(const uint32_t*)(vbp + 8);
                mma16816(oacc[nn], af, bf);
            }
        }
    }

    float inv0 = 1.0f / l0, inv1 = 1.0f / l1;
    #pragma unroll
    for (int nn = 0; nn < 8; nn++) {
        int d0 = h * HD + nn * 8 + tq;
        *(__half2*)&outH[(size_t)q0 * HH + d0] =
            __floats2half2_rn(oacc[nn][0] * inv0, oacc[nn][1] * inv0);
        *(__half2*)&outH[(size_t)(q0 + 8) * HH + d0] =
            __floats2half2_rn(oacc[nn][2] * inv1, oacc[nn][3] * inv1);
    }
}

// ---------------- fp16 MMA GEMM, cp.async 3-stage pipeline, K-tile 64 ----------------
// row stride 144 B (64 halfs + 8 pad) -> ldsm banks 4r mod 32, conflict-free
#define STG    3
#define ROWB   144
#define SBUF   (128 * ROWB)            // bytes per operand per stage (18432)
#define GEMM_SMEM (2 * STG * SBUF)     // 110592

template<int MODE, bool AG, bool GR, int SPLITK>
__global__ __launch_bounds__(256) void gemm_kernel(
    const h16* __restrict__ Aall, const h16* __restrict__ Ball,
    float* __restrict__ Cf, const float* __restrict__ Dadd,
    h16* __restrict__ OutH, int halfW,
    float* __restrict__ OutAtom,
    int M0, int N, int K,
    long long Asl, long long Bsl, long long OslH) {

    int zz = blockIdx.z;
    int e  = GR ? (zz / SPLITK) : 0;
    int ks = GR ? (zz % SPLITK) : zz;
    int M = GR ? g_cnt[e] : M0;
    if ((int)blockIdx.y * 128 >= M) return;
    const int Keff = K / SPLITK;
    const int koff = ks * Keff;
    const h16* B = Ball + (size_t)e * Bsl;

    extern __shared__ __align__(16) h16 smg[];
    h16* As = smg;                          // STG stages of 128*72 halfs
    h16* Bs = smg + STG * 128 * (ROWB / 2);

    const int tid = threadIdx.x;
    const int lane = tid & 31;
    const int wid = tid >> 5;
    const int warp_m = (wid >> 2) * 64;
    const int warp_n = (wid & 3) * 32;
    const int row0 = blockIdx.y * 128;
    const int col0 = blockIdx.x * 128;

    const int lr = tid >> 1;               // 2 threads per row
    const int lch = (tid & 1) * 32;        // halfs within 64-wide k-tile
    int arow = row0 + lr; if (arow >= M) arow = M - 1;
    const h16* aptr;
    if (AG) {
        int t = g_tok[e * TT + arow];
        aptr = Aall + (size_t)t * K + koff + lch;
    } else {
        aptr = Aall + (size_t)e * Asl + (size_t)arow * K + koff + lch;
    }
    const h16* bptr = B + (size_t)(col0 + lr) * K + koff + lch;

    uint32_t asm_base = (uint32_t)__cvta_generic_to_shared(As);
    uint32_t bsm_base = (uint32_t)__cvta_generic_to_shared(Bs);
    uint32_t ast = asm_base + (uint32_t)(lr * ROWB + lch * 2);
    uint32_t bst = bsm_base + (uint32_t)(lr * ROWB + lch * 2);
    uint32_t aoff = asm_base + (uint32_t)((warp_m + (lane & 15)) * ROWB + ((lane >> 4) << 4));
    uint32_t boff = bsm_base + (uint32_t)((warp_n + (lane & 7) + ((lane >> 4) << 3)) * ROWB
                                          + (((lane >> 3) & 1) << 4));

    const int nt = Keff >> 6;

    // prologue: stages 0,1 (4 x 16B per operand per thread)
    #pragma unroll
    for (int c = 0; c < 4; c++) {
        cpasync16(ast + c * 16, aptr + c * 8);
        cpasync16(bst + c * 16, bptr + c * 8);
    }
    cp_commit();
    if (nt > 1) {
        #pragma unroll
        for (int c = 0; c < 4; c++) {
            cpasync16(ast + SBUF + c * 16, aptr + 64 + c * 8);
            cpasync16(bst + SBUF + c * 16, bptr + 64 + c * 8);
        }
    }
    cp_commit();

    float acc[4][4][4] = {};
    const int r  = lane >> 2;
    const int tq = (lane & 3) * 2;
    int buf = 0, nxt = 2;
    for (int kt = 0; kt < nt; kt++) {
        cp_wait<1>();
        __syncthreads();
        if (kt + 2 < nt) {
            uint32_t so = (uint32_t)nxt * SBUF;
            const h16* ap = aptr + (kt + 2) * 64;
            const h16* bp = bptr + (kt + 2) * 64;
            #pragma unroll
            for (int c = 0; c < 4; c++) {
                cpasync16(ast + so + c * 16, ap + c * 8);
                cpasync16(bst + so + c * 16, bp + c * 8);
            }
        }
        cp_commit();

        uint32_t abase = aoff + (uint32_t)buf * SBUF;
        uint32_t bbase = boff + (uint32_t)buf * SBUF;
        #pragma unroll
        for (int ksub = 0; ksub < 4; ksub++) {
            const uint32_t kbb = ksub * 32;
            uint32_t afr[4][4], bfr2[2][4];
            #pragma unroll
            for (int mt = 0; mt < 4; mt++)
                ldsm4(afr[mt], abase + mt * (16 * ROWB) + kbb);
            #pragma unroll
            for (int pr = 0; pr < 2; pr++)
                ldsm4(bfr2[pr], bbase + pr * (16 * ROWB) + kbb);
            #pragma unroll
            for (int mt = 0; mt < 4; mt++) {
                #pragma unroll
                for (int nn = 0; nn < 4; nn++) {
                    uint32_t bf[2] = { bfr2[nn >> 1][(nn & 1) * 2],
                                       bfr2[nn >> 1][(nn & 1) * 2 + 1] };
                    mma16816(acc[mt][nn], afr[mt], bf);
                }
            }
        }
        buf = (buf + 1 == STG) ? 0 : buf + 1;
        nxt = (nxt + 1 == STG) ? 0 : nxt + 1;
    }

    const int* tok = g_tok + e * TT;
    const float* wt = g_wt + e * TT;
    h16* outh = (MODE == 1) ? (OutH + (size_t)e * OslH) : OutH;

    #pragma unroll
    for (int mt = 0; mt < 4; mt++) {
        #pragma unroll
        for (int nn = 0; nn < 4; nn++) {
            int rr0 = row0 + warp_m + mt * 16 + r;
            int rr1 = rr0 + 8;
            int cc  = col0 + warp_n + nn * 8 + tq;
            if (MODE == 0 && SPLITK == 1) {
                if (rr0 < M) {
                    float2 v = make_float2(acc[mt][nn][0], acc[mt][nn][1]);
                    if (Dadd) { v.x += Dadd[(size_t)rr0 * N + cc]; v.y += Dadd[(size_t)rr0 * N + cc + 1]; }
                    *(float2*)&Cf[(size_t)rr0 * N + cc] = v;
                }
                if (rr1 < M) {
                    float2 v = make_float2(acc[mt][nn][2], acc[mt][nn][3]);
                    if (Dadd) { v.x += Dadd[(size_t)rr1 * N + cc]; v.y += Dadd[(size_t)rr1 * N + cc + 1]; }
                    *(float2*)&Cf[(size_t)rr1 * N + cc] = v;
                }
            } else if (MODE == 0) {
                if (rr0 < M) {
                    atomicAdd(&Cf[(size_t)rr0 * N + cc],     acc[mt][nn][0]);
                    atomicAdd(&Cf[(size_t)rr0 * N + cc + 1], acc[mt][nn][1]);
                }
                if (rr1 < M) {
                    atomicAdd(&Cf[(size_t)rr1 * N + cc],     acc[mt][nn][2]);
                    atomicAdd(&Cf[(size_t)rr1 * N + cc + 1], acc[mt][nn][3]);
                }
            } else if (MODE == 1) {
                int j = cc >> 1;
                if (rr0 < M) {
                    float g = acc[mt][nn][0], u = acc[mt][nn][1];
                    outh[(size_t)rr0 * halfW + j] = __float2half(g / (1.0f + __expf(-g)) * u);
                }
                if (rr1 < M) {
                    float g = acc[mt][nn][2], u = acc[mt][nn][3];
                    outh[(size_t)rr1 * halfW + j] = __float2half(g / (1.0f + __expf(-g)) * u);
                }
            } else {
                if (rr0 < M) {
                    int t = tok[rr0]; float w = wt[rr0];
                    atomicAdd(&OutAtom[(size_t)t * N + cc],     w * acc[mt][nn][0]);
                    atomicAdd(&OutAtom[(size_t)t * N + cc + 1], w * acc[mt][nn][1]);
                }
                if (rr1 < M) {
                    int t = tok[rr1]; float w = wt[rr1];
                    atomicAdd(&OutAtom[(size_t)t * N + cc],     w * acc[mt][nn][2]);
                    atomicAdd(&OutAtom[(size_t)t * N + cc + 1], w * acc[mt][nn][3]);
                }
            }
        }
    }
}

// ---------------- MoE routing ----------------
__global__ void gate_kernel(const float* __restrict__ m, const float* __restrict__ gw) {
    int t = blockIdx.x;
    __shared__ float logits[NE];
    int warp = threadIdx.x >> 5, lane = threadIdx.x & 31;
    const float* xr = m + (size_t)t * HH;
    const float* wr = gw + (size_t)warp * HH;
    float s = 0.0f;
    for (int i = lane; i < HH; i += 32) s += xr[i] * wr[i];
    for (int o = 16; o > 0; o >>= 1) s += __shfl_down_sync(0xffffffffu, s, o);
    if (lane == 0) logits[warp] = s;
    __syncthreads();
    if (threadIdx.x == 0) {
        float mx = logits[0];
        for (int e = 1; e < NE; e++) mx = fmaxf(mx, logits[e]);
        float p[NE]; float sum = 0.0f;
        for (int e = 0; e < NE; e++) { p[e] = __expf(logits[e] - mx); sum += p[e]; }
        for (int e = 0; e < NE; e++) p[e] /= sum;
        int i0 = 0;
        for (int e = 1; e < NE; e++) if (p[e] > p[i0]) i0 = e;
        int i1 = (i0 == 0) ? 1 : 0;
        for (int e = 0; e < NE; e++) if (e != i0 && p[e] > p[i1]) i1 = e;
        float inv = 1.0f / (p[i0] + p[i1]);
        int pos0 = atomicAdd(&g_cnt[i0], 1);
        g_tok[i0 * TT + pos0] = t; g_wt[i0 * TT + pos0] = p[i0] * inv;
        int pos1 = atomicAdd(&g_cnt[i1], 1);
        g_tok[i1 * TT + pos1] = t; g_wt[i1 * TT + pos1] = p[i1] * inv;
    }
}

// ---------------- launch ----------------
extern "C" void kernel_launch(void* const* d_in, const int* in_sizes, int n_in,
                              void* d_out, int out_size) {
    (void)in_sizes; (void)n_in; (void)out_size;
    const int*   positions = (const int*)  d_in[0];
    const float* hidden    = (const float*)d_in[1];
    const float* input_ln  = (const float*)d_in[2];
    const float* post_ln   = (const float*)d_in[3];
    const float* resid_ln  = (const float*)d_in[4];
    const float* qkv_w     = (const float*)d_in[5];
    const float* o_w       = (const float*)d_in[6];
    const float* gate_w    = (const float*)d_in[7];
    const float* ws        = (const float*)d_in[8];
    const float* w2s       = (const float*)d_in[9];
    const float* w13       = (const float*)d_in[10];
    const float* w2        = (const float*)d_in[11];
    float* out = (float*)d_out;

    float *p_qkv, *p_resattn, *p_m;
    h16 *p_sh, *p_smh, *p_sattn, *p_ssilu, *p_sqkvw, *p_sow, *p_sw13i, *p_sw2, *p_swsi, *p_sw2s, *p_sact;
    cudaGetSymbolAddress((void**)&p_qkv,     g_qkv);
    cudaGetSymbolAddress((void**)&p_resattn, g_resattn);
    cudaGetSymbolAddress((void**)&p_m,       g_m);
    cudaGetSymbolAddress((void**)&p_sh,      s_h);
    cudaGetSymbolAddress((void**)&p_smh,     s_mh);
    cudaGetSymbolAddress((void**)&p_sattn,   s_attn);
    cudaGetSymbolAddress((void**)&p_ssilu,   s_silu);
    cudaGetSymbolAddress((void**)&p_sqkvw,   s_qkvw);
    cudaGetSymbolAddress((void**)&p_sow,     s_ow);
    cudaGetSymbolAddress((void**)&p_sw13i,   s_w13i);
    cudaGetSymbolAddress((void**)&p_sw2,     s_w2);
    cudaGetSymbolAddress((void**)&p_swsi,    s_wsi);
    cudaGetSymbolAddress((void**)&p_sw2s,    s_w2s);
    cudaGetSymbolAddress((void**)&p_sact,    s_act);

    static cudaStream_t sB = nullptr, sC = nullptr;
    static cudaEvent_t e0 = nullptr, eQkvw = nullptr, eConv = nullptr, eRes = nullptr,
                       eCpR = nullptr, eCp2 = nullptr, eMoE = nullptr;
    if (sB == nullptr) {
        cudaStreamCreateWithFlags(&sB, cudaStreamNonBlocking);
        cudaStreamCreateWithFlags(&sC, cudaStreamNonBlocking);
        cudaEventCreateWithFlags(&e0,    cudaEventDisableTiming);
        cudaEventCreateWithFlags(&eQkvw, cudaEventDisableTiming);
        cudaEventCreateWithFlags(&eConv, cudaEventDisableTiming);
        cudaEventCreateWithFlags(&eRes,  cudaEventDisableTiming);
        cudaEventCreateWithFlags(&eCpR,  cudaEventDisableTiming);
        cudaEventCreateWithFlags(&eCp2,  cudaEventDisableTiming);
        cudaEventCreateWithFlags(&eMoE,  cudaEventDisableTiming);
        cudaFuncSetAttribute(attn_mma_kernel, cudaFuncAttributeMaxDynamicSharedMemorySize, ATT_SMEM);
        cudaFuncSetAttribute((gemm_kernel<0, false, false, 1>), cudaFuncAttributeMaxDynamicSharedMemorySize, GEMM_SMEM);
        cudaFuncSetAttribute((gemm_kernel<0, false, false, 2>), cudaFuncAttributeMaxDynamicSharedMemorySize, GEMM_SMEM);
        cudaFuncSetAttribute((gemm_kernel<1, false, false, 1>), cudaFuncAttributeMaxDynamicSharedMemorySize, GEMM_SMEM);
        cudaFuncSetAttribute((gemm_kernel<1, true, true, 1>),   cudaFuncAttributeMaxDynamicSharedMemorySize, GEMM_SMEM);
        cudaFuncSetAttribute((gemm_kernel<2, false, true, 2>),  cudaFuncAttributeMaxDynamicSharedMemorySize, GEMM_SMEM);
    }

    // fork: stream B converts qkv_w FIRST, then the rest
    cudaEventRecord(e0, 0);
    cudaStreamWaitEvent(sB, e0, 0);
    conv_kernel<<<592, 256, 0, sB>>>(qkv_w, p_sqkvw, (long long)QKVD * HH / 16);
    cudaEventRecord(eQkvw, sB);
    conv_kernel<<<592, 256, 0, sB>>>(o_w, p_sow, (long long)HH * HH / 16);
    conv_interleave_kernel<<<(2 * HH * HH / 16 + 255) / 256, 256, 0, sB>>>(w13, p_sw13i, HH, HH, 1);
    conv_kernel<<<592, 256, 0, sB>>>(w2, p_sw2, (long long)HH * HH / 16);
    conv_interleave_kernel<<<((long long)NE * 2 * NI * HH / 16 + 255) / 256, 256, 0, sB>>>(ws, p_swsi, HH, NI, NE);
    conv_kernel<<<592, 256, 0, sB>>>(w2s, p_sw2s, (long long)NE * HH * NI / 16);
    cudaEventRecord(eConv, sB);

    // stream C: zero counters + pre-init resattn = hidden (for split-K o-proj)
    cudaStreamWaitEvent(sC, e0, 0);
    zero_cnt_kernel<<<1, 32, 0, sC>>>();
    copy_kernel<<<592, 256, 0, sC>>>(hidden, p_resattn, (long long)TT * HH / 4);
    cudaEventRecord(eCpR, sC);

    // main stream: rmsnorm concurrent with qkv conversion
    rmsnorm_h_kernel<<<TT, 256>>>(hidden, input_ln, p_sh);
    cudaStreamWaitEvent(0, eQkvw, 0);
    gemm_kernel<0, false, false, 1><<<dim3(QKVD / 128, TT / 128), 256, GEMM_SMEM>>>(
        p_sh, p_sqkvw, p_qkv, nullptr, nullptr, 0, nullptr, TT, QKVD, HH, 0, 0, 0);
    rope_kernel<<<(TT * (NHQ + NKVH) * 32 + 255) / 256, 256>>>(p_qkv, positions);
    attn_mma_kernel<<<dim3(TT / 128, NHQ), 256, ATT_SMEM>>>(p_qkv, p_sattn);

    // o-proj: split-K=2, atomic accumulate into pre-initialized resattn
    cudaStreamWaitEvent(0, eConv, 0);
    cudaStreamWaitEvent(0, eCpR, 0);
    gemm_kernel<0, false, false, 2><<<dim3(HH / 128, TT / 128, 2), 256, GEMM_SMEM>>>(
        p_sattn, p_sow, p_resattn, nullptr, nullptr, 0, nullptr, TT, HH, HH, 0, 0, 0);
    cudaEventRecord(eRes, 0);

    // stream B: pre-init out = resattn (base for w2 + MoE atomics)
    cudaStreamWaitEvent(sB, eRes, 0);
    copy_kernel<<<592, 256, 0, sB>>>(p_resattn, out, (long long)TT * HH / 4);
    cudaEventRecord(eCp2, sB);

    // MoE branch on stream C
    cudaStreamWaitEvent(sC, eRes, 0);
    rmsnorm_fh_kernel<<<TT, 256, 0, sC>>>(p_resattn, post_ln, p_m, p_smh);
    gate_kernel<<<TT, 256, 0, sC>>>(p_m, gate_w);
    gemm_kernel<1, true, true, 1><<<dim3(2 * NI / 128, TT / 128, NE), 256, GEMM_SMEM, sC>>>(
        p_smh, p_swsi, nullptr, nullptr, p_sact, NI, nullptr,
        TT, 2 * NI, HH,
        0, (long long)2 * NI * HH, (long long)TT * NI);
    cudaStreamWaitEvent(sC, eCp2, 0);
    gemm_kernel<2, false, true, 2><<<dim3(HH / 128, TT / 128, NE * 2), 256, GEMM_SMEM, sC>>>(
        p_sact, p_sw2s, nullptr, nullptr, nullptr, 0, out,
        TT, HH, NI,
        (long long)TT * NI, (long long)HH * NI, 0);
    cudaEventRecord(eMoE, sC);

    // MLP branch on main stream: w2 split-K atomic into out (concurrent with moe2)
    rmsnorm_h_kernel<<<TT, 256>>>(p_resattn, resid_ln, p_sh);
    gemm_kernel<1, false, false, 1><<<dim3(2 * HH / 128, TT / 128), 256, GEMM_SMEM>>>(
        p_sh, p_sw13i, nullptr, nullptr, p_ssilu, HH, nullptr, TT, 2 * HH, HH, 0, 0, 0);
    cudaStreamWaitEvent(0, eCp2, 0);
    gemm_kernel<0, false, false, 2><<<dim3(HH / 128, TT / 128, 2), 256, GEMM_SMEM>>>(
        p_ssilu, p_sw2, out, nullptr, nullptr, 0, nullptr, TT, HH, HH, 0, 0, 0);

    // join
    cudaStreamWaitEvent(0, eMoE, 0);
}

// round 15
// speedup vs baseline: 1.1489x; 1.1489x over previous
#include <cuda_runtime.h>
#include <cuda_fp16.h>
#include <math.h>
#include <stdint.h>

#define TT   2048
#define HH   1024
#define NHQ  16
#define NKVH 4
#define HD   64
#define QKVD ((NHQ + 2*NKVH) * HD)   // 1536
#define NE   8
#define NI   2048
#define EPSV 1e-5f

typedef __half h16;

// ---------------- scratch (device globals; no allocations) ----------------
__device__ float g_qkv    [(size_t)TT * QKVD];
__device__ float g_resattn[(size_t)TT * HH];
__device__ float g_m      [(size_t)TT * HH];
__device__ int   g_cnt    [NE];
__device__ int   g_tok    [NE * TT];
__device__ float g_wt     [NE * TT];

__device__ __align__(16) h16 s_h    [(size_t)TT * HH];
__device__ __align__(16) h16 s_mh   [(size_t)TT * HH];
__device__ __align__(16) h16 s_attn [(size_t)TT * HH];
__device__ __align__(16) h16 s_silu [(size_t)TT * HH];
__device__ __align__(16) h16 s_qkvw [(size_t)QKVD * HH];
__device__ __align__(16) h16 s_ow   [(size_t)HH * HH];
__device__ __align__(16) h16 s_w13i [(size_t)2 * HH * HH];
__device__ __align__(16) h16 s_w2   [(size_t)HH * HH];
__device__ __align__(16) h16 s_wsi  [(size_t)NE * 2 * NI * HH];
__device__ __align__(16) h16 s_w2s  [(size_t)NE * HH * NI];
__device__ __align__(16) h16 s_act  [(size_t)NE * TT * NI];

// ---------------- helpers ----------------
__device__ __forceinline__ void mma16816(float* c, const uint32_t* a, const uint32_t* b) {
    asm volatile(
        "mma.sync.aligned.m16n8k16.row.col.f32.f16.f16.f32 "
        "{%0,%1,%2,%3}, {%4,%5,%6,%7}, {%8,%9}, {%0,%1,%2,%3};"
        : "+f"(c[0]), "+f"(c[1]), "+f"(c[2]), "+f"(c[3])
        : "r"(a[0]), "r"(a[1]), "r"(a[2]), "r"(a[3]), "r"(b[0]), "r"(b[1]));
}

__device__ __forceinline__ void ldsm4(uint32_t* r, uint32_t addr) {
    asm volatile("ldmatrix.sync.aligned.m8n8.x4.shared.b16 {%0,%1,%2,%3}, [%4];"
        : "=r"(r[0]), "=r"(r[1]), "=r"(r[2]), "=r"(r[3]) : "r"(addr));
}

__device__ __forceinline__ void cpasync16(uint32_t dst, const void* src) {
    asm volatile("cp.async.cg.shared.global [%0], [%1], 16;" :: "r"(dst), "l"(src));
}
__device__ __forceinline__ void cp_commit() {
    asm volatile("cp.async.commit_group;");
}
template<int N>
__device__ __forceinline__ void cp_wait() {
    asm volatile("cp.async.wait_group %0;" :: "n"(N));
}

// ---------------- utility kernels ----------------
__global__ void zero_cnt_kernel() {
    if (threadIdx.x < NE) g_cnt[threadIdx.x] = 0;
}

__global__ void zero_f_kernel(float* __restrict__ dst, long long n4) {
    long long i = (long long)blockIdx.x * 256 + threadIdx.x;
    long long stride = (long long)gridDim.x * 256;
    float4 z = make_float4(0.f, 0.f, 0.f, 0.f);
    for (; i < n4; i += stride) ((float4*)dst)[i] = z;
}

__global__ void copy_kernel(const float* __restrict__ src, float* __restrict__ dst,
                            long long n4) {
    long long i = (long long)blockIdx.x * 256 + threadIdx.x;
    long long stride = (long long)gridDim.x * 256;
    for (; i < n4; i += stride)
        ((float4*)dst)[i] = ((const float4*)src)[i];
}

__global__ void conv_kernel(const float* __restrict__ in, h16* __restrict__ out,
                            long long total16) {
    long long idx = (long long)blockIdx.x * 256 + threadIdx.x;
    long long stride = (long long)gridDim.x * 256;
    for (; idx < total16; idx += stride) {
        const float4* ip = (const float4*)&in[idx * 16];
        float4 v0 = ip[0], v1 = ip[1], v2 = ip[2], v3 = ip[3];
        __half2 h[8];
        h[0] = __floats2half2_rn(v0.x, v0.y); h[1] = __floats2half2_rn(v0.z, v0.w);
        h[2] = __floats2half2_rn(v1.x, v1.y); h[3] = __floats2half2_rn(v1.z, v1.w);
        h[4] = __floats2half2_rn(v2.x, v2.y); h[5] = __floats2half2_rn(v2.z, v2.w);
        h[6] = __floats2half2_rn(v3.x, v3.y); h[7] = __floats2half2_rn(v3.z, v3.w);
        *(uint4*)&out[idx * 16]     = *(uint4*)&h[0];
        *(uint4*)&out[idx * 16 + 8] = *(uint4*)&h[4];
    }
}

__global__ void conv_interleave_kernel(const float* __restrict__ in, h16* __restrict__ out,
                                       int K, int I, int groups) {
    long long idx = (long long)blockIdx.x * 256 + threadIdx.x;
    int K16 = K >> 4;
    long long per_group = (long long)2 * I * K16;
    long long total = (long long)groups * per_group;
    if (idx >= total) return;
    int g = (int)(idx / per_group);
    long long rem = idx % per_group;
    int r = (int)(rem / K16);
    int kq = (int)(rem % K16) * 16;
    int outr = (r < I) ? (2 * r) : (2 * (r - I) + 1);
    const float4* ip = (const float4*)&in[((size_t)g * 2 * I + r) * K + kq];
    float4 v0 = ip[0], v1 = ip[1], v2 = ip[2], v3 = ip[3];
    __half2 h[8];
    h[0] = __floats2half2_rn(v0.x, v0.y); h[1] = __floats2half2_rn(v0.z, v0.w);
    h[2] = __floats2half2_rn(v1.x, v1.y); h[3] = __floats2half2_rn(v1.z, v1.w);
    h[4] = __floats2half2_rn(v2.x, v2.y); h[5] = __floats2half2_rn(v2.z, v2.w);
    h[6] = __floats2half2_rn(v3.x, v3.y); h[7] = __floats2half2_rn(v3.z, v3.w);
    h16* o = out + ((size_t)g * 2 * I + outr) * K + kq;
    *(uint4*)&o[0] = *(uint4*)&h[0];
    *(uint4*)&o[8] = *(uint4*)&h[4];
}

__global__ void rmsnorm_h_kernel(const float* __restrict__ x,
                                 const float* __restrict__ w,
                                 h16* __restrict__ o) {
    int t = blockIdx.x;
    float4 xv = ((const float4*)(x + (size_t)t * HH))[threadIdx.x];
    float s = xv.x * xv.x + xv.y * xv.y + xv.z * xv.z + xv.w * xv.w;
    __shared__ float red[256];
    red[threadIdx.x] = s;
    __syncthreads();
    for (int k = 128; k > 0; k >>= 1) {
        if (threadIdx.x < k) red[threadIdx.x] += red[threadIdx.x + k];
        __syncthreads();
    }
    float rs = rsqrtf(red[0] / (float)HH + EPSV);
    float4 wv = ((const float4*)w)[threadIdx.x];
    h16* op = o + (size_t)t * HH + threadIdx.x * 4;
    *(__half2*)&op[0] = __floats2half2_rn(xv.x * rs * wv.x, xv.y * rs * wv.y);
    *(__half2*)&op[2] = __floats2half2_rn(xv.z * rs * wv.z, xv.w * rs * wv.w);
}

__global__ void rmsnorm_fh_kernel(const float* __restrict__ x,
                                  const float* __restrict__ w,
                                  float* __restrict__ of, h16* __restrict__ oh) {
    int t = blockIdx.x;
    float4 xv = ((const float4*)(x + (size_t)t * HH))[threadIdx.x];
    float s = xv.x * xv.x + xv.y * xv.y + xv.z * xv.z + xv.w * xv.w;
    __shared__ float red[256];
    red[threadIdx.x] = s;
    __syncthreads();
    for (int k = 128; k > 0; k >>= 1) {
        if (threadIdx.x < k) red[threadIdx.x] += red[threadIdx.x + k];
        __syncthreads();
    }
    float rs = rsqrtf(red[0] / (float)HH + EPSV);
    float4 wv = ((const float4*)w)[threadIdx.x];
    float4 ov = make_float4(xv.x * rs * wv.x, xv.y * rs * wv.y, xv.z * rs * wv.z, xv.w * rs * wv.w);
    ((float4*)(of + (size_t)t * HH))[threadIdx.x] = ov;
    h16* op = oh + (size_t)t * HH + threadIdx.x * 4;
    *(__half2*)&op[0] = __floats2half2_rn(ov.x, ov.y);
    *(__half2*)&op[2] = __floats2half2_rn(ov.z, ov.w);
}

__global__ void rope_kernel(float* __restrict__ qkv, const int* __restrict__ positions) {
    int idx = blockIdx.x * 256 + threadIdx.x;
    if (idx >= TT * (NHQ + NKVH) * 32) return;
    int t = idx / ((NHQ + NKVH) * 32);
    int rem = idx % ((NHQ + NKVH) * 32);
    int h = rem >> 5;
    int d = rem & 31;
    int off = (h < NHQ) ? h * HD : NHQ * HD + (h - NHQ) * HD;
    float* p = qkv + (size_t)t * QKVD + off;
    float x1 = p[d];
    float x2 = p[d + 32];
    float pos = (float)positions[t];
    float invf = __expf(-0.2878231366f * (float)d);   // ln(10000)/32
    float fr = pos * invf;
    float c, s;
    __sincosf(fr, &s, &c);
    p[d]      = x1 * c - x2 * s;
    p[d + 32] = x2 * c + x1 * s;
}

// ---------------- flash attention: BR=128 x BC=64, register softmax, f16x2 ex2 ----------------
#define ATT_SMEM ((128 + 64 + 64) * 72 * 2)

__global__ __launch_bounds__(256) void attn_mma_kernel(
    const float* __restrict__ qkv, h16* __restrict__ outH) {
    extern __shared__ char smraw[];
    h16* Qh = (h16*)smraw;
    h16* Kh = Qh + 128 * 72;
    h16* Vh = Kh + 64 * 72;

    int qblk = gridDim.x - 1 - blockIdx.x;
    int h = blockIdx.y;
    int kvh = h >> 2;
    int tid = threadIdx.x, lane = tid & 31, w = tid >> 5;
    int r = lane >> 2, tq = (lane & 3) * 2;
    int q0 = qblk * 128 + w * 16 + r;

    for (int i = tid; i < 128 * 16; i += 256) {
        int row = i >> 4, c = (i & 15) << 2;
        float4 v = *(const float4*)&qkv[(size_t)(qblk * 128 + row) * QKVD + h * HD + c];
        h16* qp = Qh + row * 72 + c;
        *(__half2*)&qp[0] = __floats2half2_rn(v.x, v.y);
        *(__half2*)&qp[2] = __floats2half2_rn(v.z, v.w);
    }

    const float c2 = 0.18033688011112042f;
    float m0 = -1e30f, m1 = -1e30f, l0 = 0.f, l1 = 0.f;
    float oacc[8][4] = {};

    int ktmax = qblk * 2 + 1;
    for (int kt = 0; kt <= ktmax; kt++) {
        __syncthreads();
        for (int i = tid; i < 64 * 16; i += 256) {
            int row = i >> 4, c = (i & 15) << 2;
            size_t base = (size_t)(kt * 64 + row) * QKVD + NHQ * HD + kvh * HD;
            float4 kv = *(const float4*)&qkv[base + c];
            h16* kp = Kh + row * 72 + c;
            *(__half2*)&kp[0] = __floats2half2_rn(kv.x, kv.y);
            *(__half2*)&kp[2] = __floats2half2_rn(kv.z, kv.w);
            float4 vv = *(const float4*)&qkv[base + NKVH * HD + c];
            Vh[(c + 0) * 72 + row] = __float2half(vv.x);
            Vh[(c + 1) * 72 + row] = __float2half(vv.y);
            Vh[(c + 2) * 72 + row] = __float2half(vv.z);
            Vh[(c + 3) * 72 + row] = __float2half(vv.w);
        }
        __syncthreads();

        float sacc[8][4] = {};
        #pragma unroll
        for (int kb = 0; kb < 4; kb++) {
            int kbo = kb * 16;
            uint32_t af[4];
            const h16* qb = Qh + (w * 16 + r) * 72 + kbo + tq;
            af[0] = *(const uint32_t*)qb;
            af[1] = *(const uint32_t*)(qb + 8 * 72);
            af[2] = *(const uint32_t*)(qb + 8);
            af[3] = *(const uint32_t*)(qb + 8 * 72 + 8);
            #pragma unroll
            for (int nn = 0; nn < 8; nn++) {
                uint32_t bf[2];
                const h16* kbp = Kh + (nn * 8 + r) * 72 + kbo + tq;
                bf[0] = *(const uint32_t*)kbp;
                bf[1] = *(const uint32_t*)(kbp + 8);
                mma16816(sacc[nn], af, bf);
            }
        }

        int colb = kt * 64;
        if ((colb + 63) > q0) {
            #pragma unroll
            for (int nn = 0; nn < 8; nn++) {
                int c0 = colb + nn * 8 + tq;
                sacc[nn][0] = (c0     <= q0    ) ? sacc[nn][0] * c2 : -1e30f;
                sacc[nn][1] = (c0 + 1 <= q0    ) ? sacc[nn][1] * c2 : -1e30f;
                sacc[nn][2] = (c0     <= q0 + 8) ? sacc[nn][2] * c2 : -1e30f;
                sacc[nn][3] = (c0 + 1 <= q0 + 8) ? sacc[nn][3] * c2 : -1e30f;
            }
        } else {
            #pragma unroll
            for (int nn = 0; nn < 8; nn++) {
                sacc[nn][0] *= c2; sacc[nn][1] *= c2;
                sacc[nn][2] *= c2; sacc[nn][3] *= c2;
            }
        }

        float mt0 = -1e30f, mt1 = -1e30f;
        #pragma unroll
        for (int nn = 0; nn < 8; nn++) {
            mt0 = fmaxf(mt0, fmaxf(sacc[nn][0], sacc[nn][1]));
            mt1 = fmaxf(mt1, fmaxf(sacc[nn][2], sacc[nn][3]));
        }
        mt0 = fmaxf(mt0, __shfl_xor_sync(0xffffffffu, mt0, 1));
        mt0 = fmaxf(mt0, __shfl_xor_sync(0xffffffffu, mt0, 2));
        mt1 = fmaxf(mt1, __shfl_xor_sync(0xffffffffu, mt1, 1));
        mt1 = fmaxf(mt1, __shfl_xor_sync(0xffffffffu, mt1, 2));
        float nm0 = fmaxf(m0, mt0), nm1 = fmaxf(m1, mt1);
        float corr0 = exp2f(m0 - nm0), corr1 = exp2f(m1 - nm1);
        m0 = nm0; m1 = nm1;

        uint32_t pa[8], pb[8];
        float s0 = 0.f, s1 = 0.f;
        #pragma unroll
        for (int nn = 0; nn < 8; nn++) {
            __half2 ta = __floats2half2_rn(sacc[nn][0] - nm0, sacc[nn][1] - nm0);
            __half2 tb = __floats2half2_rn(sacc[nn][2] - nm1, sacc[nn][3] - nm1);
            uint32_t ua, ub;
            asm("ex2.approx.f16x2 %0, %1;" : "=r"(ua) : "r"(*(uint32_t*)&ta));
            asm("ex2.approx.f16x2 %0, %1;" : "=r"(ub) : "r"(*(uint32_t*)&tb));
            pa[nn] = ua; pb[nn] = ub;
            float2 fa = __half22float2(*(__half2*)&ua);
            float2 fb = __half22float2(*(__half2*)&ub);
            s0 += fa.x + fa.y; s1 += fb.x + fb.y;
        }
        s0 += __shfl_xor_sync(0xffffffffu, s0, 1);
        s0 += __shfl_xor_sync(0xffffffffu, s0, 2);
        s1 += __shfl_xor_sync(0xffffffffu, s1, 1);
        s1 += __shfl_xor_sync(0xffffffffu, s1, 2);
        l0 = l0 * corr0 + s0;
        l1 = l1 * corr1 + s1;

        #pragma unroll
        for (int nn = 0; nn < 8; nn++) {
            oacc[nn][0] *= corr0; oacc[nn][1] *= corr0;
            oacc[nn][2] *= corr1; oacc[nn][3] *= corr1;
        }
        #pragma unroll
        for (int kb = 0; kb < 4; kb++) {
            uint32_t af[4] = { pa[2 * kb], pb[2 * kb], pa[2 * kb + 1], pb[2 * kb + 1] };
            int kbo = kb * 16;
            #pragma unroll
            for (int nn = 0; nn < 8; nn++) {
                uint32_t bf[2];
                const h16* vbp = Vh + (nn * 8 + r) * 72 + kbo + tq;
                bf[0] = *(const uint32_t*)vbp;
                bf[1] = *(const uint32_t*)(vbp + 8);
                mma16816(oacc[nn], af, bf);
            }
        }
    }

    float inv0 = 1.0f / l0, inv1 = 1.0f / l1;
    #pragma unroll
    for (int nn = 0; nn < 8; nn++) {
        int d0 = h * HD + nn * 8 + tq;
        *(__half2*)&outH[(size_t)q0 * HH + d0] =
            __floats2half2_rn(oacc[nn][0] * inv0, oacc[nn][1] * inv0);
        *(__half2*)&outH[(size_t)(q0 + 8) * HH + d0] =
            __floats2half2_rn(oacc[nn][2] * inv1, oacc[nn][3] * inv1);
    }
}

// ---------------- fp16 MMA GEMM, cp.async 3-stage pipeline, optional split-K ----------------
#define STG    3
#define SBUF   (128 * 40 * 2)
#define GEMM_SMEM (2 * STG * SBUF)

template<int MODE, bool AG, bool GR, int SPLITK>
__global__ __launch_bounds__(256) void gemm_kernel(
    const h16* __restrict__ Aall, const h16* __restrict__ Ball,
    float* __restrict__ Cf, const float* __restrict__ Dadd,
    h16* __restrict__ OutH, int halfW,
    float* __restrict__ OutAtom,
    int M0, int N, int K,
    long long Asl, long long Bsl, long long OslH) {

    int zz = blockIdx.z;
    int e  = GR ? (zz / SPLITK) : 0;
    int ks = GR ? (zz % SPLITK) : zz;
    int M = GR ? g_cnt[e] : M0;
    if ((int)blockIdx.y * 128 >= M) return;
    const int Keff = K / SPLITK;
    const int koff = ks * Keff;
    const h16* B = Ball + (size_t)e * Bsl;

    extern __shared__ __align__(16) h16 smg[];
    h16* As = smg;
    h16* Bs = smg + STG * 128 * 40;

    const int tid = threadIdx.x;
    const int lane = tid & 31;
    const int wid = tid >> 5;
    const int warp_m = (wid >> 2) * 64;
    const int warp_n = (wid & 3) * 32;
    const int row0 = blockIdx.y * 128;
    const int col0 = blockIdx.x * 128;

    const int lr = tid >> 1;
    const int lc = (tid & 1) * 16;
    int arow = row0 + lr; if (arow >= M) arow = M - 1;
    const h16* aptr;
    if (AG) {
        int t = g_tok[e * TT + arow];
        aptr = Aall + (size_t)t * K + koff + lc;
    } else {
        aptr = Aall + (size_t)e * Asl + (size_t)arow * K + koff + lc;
    }
    const h16* bptr = B + (size_t)(col0 + lr) * K + koff + lc;

    uint32_t asm_base = (uint32_t)__cvta_generic_to_shared(As);
    uint32_t bsm_base = (uint32_t)__cvta_generic_to_shared(Bs);
    uint32_t ast = asm_base + (uint32_t)(lr * 80 + lc * 2);
    uint32_t bst = bsm_base + (uint32_t)(lr * 80 + lc * 2);
    uint32_t aoff = asm_base + (uint32_t)((warp_m + (lane & 15)) * 80 + ((lane >> 4) << 4));
    uint32_t boff = bsm_base + (uint32_t)((warp_n + (lane & 7) + ((lane >> 4) << 3)) * 80
                                          + (((lane >> 3) & 1) << 4));

    const int nt = Keff >> 5;

    cpasync16(ast, aptr);            cpasync16(ast + 16, aptr + 8);
    cpasync16(bst, bptr);            cpasync16(bst + 16, bptr + 8);
    cp_commit();
    if (nt > 1) {
        cpasync16(ast + SBUF, aptr + 32);      cpasync16(ast + SBUF + 16, aptr + 40);
        cpasync16(bst + SBUF, bptr + 32);      cpasync16(bst + SBUF + 16, bptr + 40);
    }
    cp_commit();

    float acc[4][4][4] = {};
    const int r  = lane >> 2;
    const int tq = (lane & 3) * 2;
    int buf = 0, nxt = 2;
    for (int kt = 0; kt < nt; kt++) {
        cp_wait<1>();
        __syncthreads();
        if (kt + 2 < nt) {
            uint32_t so = (uint32_t)nxt * SBUF;
            const h16* ap = aptr + (kt + 2) * 32;
            const h16* bp = bptr + (kt + 2) * 32;
            cpasync16(ast + so, ap);       cpasync16(ast + so + 16, ap + 8);
            cpasync16(bst + so, bp);       cpasync16(bst + so + 16, bp + 8);
        }
        cp_commit();

        uint32_t abase = aoff + (uint32_t)buf * SBUF;
        uint32_t bbase = boff + (uint32_t)buf * SBUF;
        #pragma unroll
        for (int ksub = 0; ksub < 2; ksub++) {
            const uint32_t kbb = ksub * 32;
            uint32_t afr[4][4], bfr2[2][4];
            #pragma unroll
            for (int mt = 0; mt < 4; mt++)
                ldsm4(afr[mt], abase + mt * (16 * 80) + kbb);
            #pragma unroll
            for (int pr = 0; pr < 2; pr++)
                ldsm4(bfr2[pr], bbase + pr * (16 * 80) + kbb);
            #pragma unroll
            for (int mt = 0; mt < 4; mt++) {
                #pragma unroll
                for (int nn = 0; nn < 4; nn++) {
                    uint32_t bf[2] = { bfr2[nn >> 1][(nn & 1) * 2],
                                       bfr2[nn >> 1][(nn & 1) * 2 + 1] };
                    mma16816(acc[mt][nn], afr[mt], bf);
                }
            }
        }
        buf = (buf + 1 == STG) ? 0 : buf + 1;
        nxt = (nxt + 1 == STG) ? 0 : nxt + 1;
    }

    const int* tok = g_tok + e * TT;
    const float* wt = g_wt + e * TT;
    h16* outh = (MODE == 1) ? (OutH + (size_t)e * OslH) : OutH;

    #pragma unroll
    for (int mt = 0; mt < 4; mt++) {
        #pragma unroll
        for (int nn = 0; nn < 4; nn++) {
            int rr0 = row0 + warp_m + mt * 16 + r;
            int rr1 = rr0 + 8;
            int cc  = col0 + warp_n + nn * 8 + tq;
            if (MODE == 0 && SPLITK == 1) {
                if (rr0 < M) {
                    float2 v = make_float2(acc[mt][nn][0], acc[mt][nn][1]);
                    if (Dadd) { v.x += Dadd[(size_t)rr0 * N + cc]; v.y += Dadd[(size_t)rr0 * N + cc + 1]; }
                    *(float2*)&Cf[(size_t)rr0 * N + cc] = v;
                }
                if (rr1 < M) {
                    float2 v = make_float2(acc[mt][nn][2], acc[mt][nn][3]);
                    if (Dadd) { v.x += Dadd[(size_t)rr1 * N + cc]; v.y += Dadd[(size_t)rr1 * N + cc + 1]; }
                    *(float2*)&Cf[(size_t)rr1 * N + cc] = v;
                }
            } else if (MODE == 0) {
                if (rr0 < M) {
                    atomicAdd(&Cf[(size_t)rr0 * N + cc],     acc[mt][nn][0]);
                    atomicAdd(&Cf[(size_t)rr0 * N + cc + 1], acc[mt][nn][1]);
                }
                if (rr1 < M) {
                    atomicAdd(&Cf[(size_t)rr1 * N + cc],     acc[mt][nn][2]);
                    atomicAdd(&Cf[(size_t)rr1 * N + cc + 1], acc[mt][nn][3]);
                }
            } else if (MODE == 1) {
                int j = cc >> 1;
                if (rr0 < M) {
                    float g = acc[mt][nn][0], u = acc[mt][nn][1];
                    outh[(size_t)rr0 * halfW + j] = __float2half(g / (1.0f + __expf(-g)) * u);
                }
                if (rr1 < M) {
                    float g = acc[mt][nn][2], u = acc[mt][nn][3];
                    outh[(size_t)rr1 * halfW + j] = __float2half(g / (1.0f + __expf(-g)) * u);
                }
            } else {
                if (rr0 < M) {
                    int t = tok[rr0]; float w = wt[rr0];
                    atomicAdd(&OutAtom[(size_t)t * N + cc],     w * acc[mt][nn][0]);
                    atomicAdd(&OutAtom[(size_t)t * N + cc + 1], w * acc[mt][nn][1]);
                }
                if (rr1 < M) {
                    int t = tok[rr1]; float w = wt[rr1];
                    atomicAdd(&OutAtom[(size_t)t * N + cc],     w * acc[mt][nn][2]);
                    atomicAdd(&OutAtom[(size_t)t * N + cc + 1], w * acc[mt][nn][3]);
                }
            }
        }
    }
}

// ---------------- MoE routing ----------------
__global__ void gate_kernel(const float* __restrict__ m, const float* __restrict__ gw) {
    int t = blockIdx.x;
    __shared__ float logits[NE];
    int warp = threadIdx.x >> 5, lane = threadIdx.x & 31;
    const float* xr = m + (size_t)t * HH;
    const float* wr = gw + (size_t)warp * HH;
    float s = 0.0f;
    for (int i = lane; i < HH; i += 32) s += xr[i] * wr[i];
    for (int o = 16; o > 0; o >>= 1) s += __shfl_down_sync(0xffffffffu, s, o);
    if (lane == 0) logits[warp] = s;
    __syncthreads();
    if (threadIdx.x == 0) {
        float mx = logits[0];
        for (int e = 1; e < NE; e++) mx = fmaxf(mx, logits[e]);
        float p[NE]; float sum = 0.0f;
        for (int e = 0; e < NE; e++) { p[e] = __expf(logits[e] - mx); sum += p[e]; }
        for (int e = 0; e < NE; e++) p[e] /= sum;
        int i0 = 0;
        for (int e = 1; e < NE; e++) if (p[e] > p[i0]) i0 = e;
        int i1 = (i0 == 0) ? 1 : 0;
        for (int e = 0; e < NE; e++) if (e != i0 && p[e] > p[i1]) i1 = e;
        float inv = 1.0f / (p[i0] + p[i1]);
        int pos0 = atomicAdd(&g_cnt[i0], 1);
        g_tok[i0 * TT + pos0] = t; g_wt[i0 * TT + pos0] = p[i0] * inv;
        int pos1 = atomicAdd(&g_cnt[i1], 1);
        g_tok[i1 * TT + pos1] = t; g_wt[i1 * TT + pos1] = p[i1] * inv;
    }
}

// ---------------- launch ----------------
extern "C" void kernel_launch(void* const* d_in, const int* in_sizes, int n_in,
                              void* d_out, int out_size) {
    (void)in_sizes; (void)n_in; (void)out_size;
    const int*   positions = (const int*)  d_in[0];
    const float* hidden    = (const float*)d_in[1];
    const float* input_ln  = (const float*)d_in[2];
    const float* post_ln   = (const float*)d_in[3];
    const float* resid_ln  = (const float*)d_in[4];
    const float* qkv_w     = (const float*)d_in[5];
    const float* o_w       = (const float*)d_in[6];
    const float* gate_w    = (const float*)d_in[7];
    const float* ws        = (const float*)d_in[8];
    const float* w2s       = (const float*)d_in[9];
    const float* w13       = (const float*)d_in[10];
    const float* w2        = (const float*)d_in[11];
    float* out = (float*)d_out;

    float *p_qkv, *p_resattn, *p_m;
    h16 *p_sh, *p_smh, *p_sattn, *p_ssilu, *p_sqkvw, *p_sow, *p_sw13i, *p_sw2, *p_swsi, *p_sw2s, *p_sact;
    cudaGetSymbolAddress((void**)&p_qkv,     g_qkv);
    cudaGetSymbolAddress((void**)&p_resattn, g_resattn);
    cudaGetSymbolAddress((void**)&p_m,       g_m);
    cudaGetSymbolAddress((void**)&p_sh,      s_h);
    cudaGetSymbolAddress((void**)&p_smh,     s_mh);
    cudaGetSymbolAddress((void**)&p_sattn,   s_attn);
    cudaGetSymbolAddress((void**)&p_ssilu,   s_silu);
    cudaGetSymbolAddress((void**)&p_sqkvw,   s_qkvw);
    cudaGetSymbolAddress((void**)&p_sow,     s_ow);
    cudaGetSymbolAddress((void**)&p_sw13i,   s_w13i);
    cudaGetSymbolAddress((void**)&p_sw2,     s_w2);
    cudaGetSymbolAddress((void**)&p_swsi,    s_wsi);
    cudaGetSymbolAddress((void**)&p_sw2s,    s_w2s);
    cudaGetSymbolAddress((void**)&p_sact,    s_act);

    static cudaStream_t sB = nullptr, sC = nullptr;
    static cudaEvent_t e0 = nullptr, eQkvw = nullptr, eConv = nullptr, eRes = nullptr,
                       eZq = nullptr, eCpR = nullptr, eCp2 = nullptr, eMoE = nullptr;
    if (sB == nullptr) {
        cudaStreamCreateWithFlags(&sB, cudaStreamNonBlocking);
        cudaStreamCreateWithFlags(&sC, cudaStreamNonBlocking);
        cudaEventCreateWithFlags(&e0,    cudaEventDisableTiming);
        cudaEventCreateWithFlags(&eQkvw, cudaEventDisableTiming);
        cudaEventCreateWithFlags(&eConv, cudaEventDisableTiming);
        cudaEventCreateWithFlags(&eRes,  cudaEventDisableTiming);
        cudaEventCreateWithFlags(&eZq,   cudaEventDisableTiming);
        cudaEventCreateWithFlags(&eCpR,  cudaEventDisableTiming);
        cudaEventCreateWithFlags(&eCp2,  cudaEventDisableTiming);
        cudaEventCreateWithFlags(&eMoE,  cudaEventDisableTiming);
        cudaFuncSetAttribute(attn_mma_kernel, cudaFuncAttributeMaxDynamicSharedMemorySize, ATT_SMEM);
        cudaFuncSetAttribute((gemm_kernel<0, false, false, 1>), cudaFuncAttributeMaxDynamicSharedMemorySize, GEMM_SMEM);
        cudaFuncSetAttribute((gemm_kernel<0, false, false, 2>), cudaFuncAttributeMaxDynamicSharedMemorySize, GEMM_SMEM);
        cudaFuncSetAttribute((gemm_kernel<1, false, false, 1>), cudaFuncAttributeMaxDynamicSharedMemorySize, GEMM_SMEM);
        cudaFuncSetAttribute((gemm_kernel<1, true, true, 1>),   cudaFuncAttributeMaxDynamicSharedMemorySize, GEMM_SMEM);
        cudaFuncSetAttribute((gemm_kernel<2, false, true, 2>),  cudaFuncAttributeMaxDynamicSharedMemorySize, GEMM_SMEM);
    }

    // fork: stream B converts qkv_w FIRST, then the rest
    cudaEventRecord(e0, 0);
    cudaStreamWaitEvent(sB, e0, 0);
    conv_kernel<<<592, 256, 0, sB>>>(qkv_w, p_sqkvw, (long long)QKVD * HH / 16);
    cudaEventRecord(eQkvw, sB);
    conv_kernel<<<592, 256, 0, sB>>>(o_w, p_sow, (long long)HH * HH / 16);
    conv_interleave_kernel<<<(2 * HH * HH / 16 + 255) / 256, 256, 0, sB>>>(w13, p_sw13i, HH, HH, 1);
    conv_kernel<<<592, 256, 0, sB>>>(w2, p_sw2, (long long)HH * HH / 16);
    conv_interleave_kernel<<<((long long)NE * 2 * NI * HH / 16 + 255) / 256, 256, 0, sB>>>(ws, p_swsi, HH, NI, NE);
    conv_kernel<<<592, 256, 0, sB>>>(w2s, p_sw2s, (long long)NE * HH * NI / 16);
    cudaEventRecord(eConv, sB);

    // stream C: zero counters, zero qkv accumulator, pre-init resattn = hidden
    cudaStreamWaitEvent(sC, e0, 0);
    zero_cnt_kernel<<<1, 32, 0, sC>>>();
    zero_f_kernel<<<592, 256, 0, sC>>>(p_qkv, (long long)TT * QKVD / 4);
    cudaEventRecord(eZq, sC);
    copy_kernel<<<592, 256, 0, sC>>>(hidden, p_resattn, (long long)TT * HH / 4);
    cudaEventRecord(eCpR, sC);

    // main stream: rmsnorm concurrent with qkv conversion
    rmsnorm_h_kernel<<<TT, 256>>>(hidden, input_ln, p_sh);
    cudaStreamWaitEvent(0, eQkvw, 0);
    cudaStreamWaitEvent(0, eZq, 0);
    // qkv: split-K=2, atomic accumulate into zeroed g_qkv (384 CTAs -> full chip)
    gemm_kernel<0, false, false, 2><<<dim3(QKVD / 128, TT / 128, 2), 256, GEMM_SMEM>>>(
        p_sh, p_sqkvw, p_qkv, nullptr, nullptr, 0, nullptr, TT, QKVD, HH, 0, 0, 0);
    rope_kernel<<<(TT * (NHQ + NKVH) * 32 + 255) / 256, 256>>>(p_qkv, positions);
    attn_mma_kernel<<<dim3(TT / 128, NHQ), 256, ATT_SMEM>>>(p_qkv, p_sattn);

    // o-proj: split-K=2, atomic accumulate into pre-initialized resattn
    cudaStreamWaitEvent(0, eConv, 0);
    cudaStreamWaitEvent(0, eCpR, 0);
    gemm_kernel<0, false, false, 2><<<dim3(HH / 128, TT / 128, 2), 256, GEMM_SMEM>>>(
        p_sattn, p_sow, p_resattn, nullptr, nullptr, 0, nullptr, TT, HH, HH, 0, 0, 0);
    cudaEventRecord(eRes, 0);

    // stream B: pre-init out = resattn (base for w2 + MoE atomics)
    cudaStreamWaitEvent(sB, eRes, 0);
    copy_kernel<<<592, 256, 0, sB>>>(p_resattn, out, (long long)TT * HH / 4);
    cudaEventRecord(eCp2, sB);

    // MoE branch on stream C
    cudaStreamWaitEvent(sC, eRes, 0);
    rmsnorm_fh_kernel<<<TT, 256, 0, sC>>>(p_resattn, post_ln, p_m, p_smh);
    gate_kernel<<<TT, 256, 0, sC>>>(p_m, gate_w);
    gemm_kernel<1, true, true, 1><<<dim3(2 * NI / 128, TT / 128, NE), 256, GEMM_SMEM, sC>>>(
        p_smh, p_swsi, nullptr, nullptr, p_sact, NI, nullptr,
        TT, 2 * NI, HH,
        0, (long long)2 * NI * HH, (long long)TT * NI);
    cudaStreamWaitEvent(sC, eCp2, 0);
    gemm_kernel<2, false, true, 2><<<dim3(HH / 128, TT / 128, NE * 2), 256, GEMM_SMEM, sC>>>(
        p_sact, p_sw2s, nullptr, nullptr, nullptr, 0, out,
        TT, HH, NI,
        (long long)TT * NI, (long long)HH * NI, 0);
    cudaEventRecord(eMoE, sC);

    // MLP branch on main stream: w2 split-K atomic into out (concurrent with moe2)
    rmsnorm_h_kernel<<<TT, 256>>>(p_resattn, resid_ln, p_sh);
    gemm_kernel<1, false, false, 1><<<dim3(2 * HH / 128, TT / 128), 256, GEMM_SMEM>>>(
        p_sh, p_sw13i, nullptr, nullptr, p_ssilu, HH, nullptr, TT, 2 * HH, HH, 0, 0, 0);
    cudaStreamWaitEvent(0, eCp2, 0);
    gemm_kernel<0, false, false, 2><<<dim3(HH / 128, TT / 128, 2), 256, GEMM_SMEM>>>(
        p_ssilu, p_sw2, out, nullptr, nullptr, 0, nullptr, TT, HH, HH, 0, 0, 0);

    // join
    cudaStreamWaitEvent(0, eMoE, 0);
}

// round 16
// speedup vs baseline: 1.1748x; 1.0225x over previous
#include <cuda_runtime.h>
#include <cuda_fp16.h>
#include <math.h>
#include <stdint.h>

#define TT   2048
#define HH   1024
#define NHQ  16
#define NKVH 4
#define HD   64
#define QKVD ((NHQ + 2*NKVH) * HD)   // 1536
#define NE   8
#define NI   2048
#define EPSV 1e-5f

typedef __half h16;

// ---------------- scratch (device globals; no allocations) ----------------
__device__ float g_resattn[(size_t)TT * HH];
__device__ float g_m      [(size_t)TT * HH];
__device__ int   g_cnt    [NE];
__device__ int   g_tok    [NE * TT];
__device__ float g_wt     [NE * TT];

__device__ __align__(16) h16 s_qkvh [(size_t)TT * QKVD];
__device__ __align__(16) h16 s_h    [(size_t)TT * HH];
__device__ __align__(16) h16 s_mh   [(size_t)TT * HH];
__device__ __align__(16) h16 s_attn [(size_t)TT * HH];
__device__ __align__(16) h16 s_silu [(size_t)TT * HH];
__device__ __align__(16) h16 s_qkvw [(size_t)QKVD * HH];
__device__ __align__(16) h16 s_ow   [(size_t)HH * HH];
__device__ __align__(16) h16 s_w13i [(size_t)2 * HH * HH];
__device__ __align__(16) h16 s_w2   [(size_t)HH * HH];
__device__ __align__(16) h16 s_wsi  [(size_t)NE * 2 * NI * HH];
__device__ __align__(16) h16 s_w2s  [(size_t)NE * HH * NI];
__device__ __align__(16) h16 s_act  [(size_t)NE * TT * NI];

// ---------------- helpers ----------------
__device__ __forceinline__ void mma16816(float* c, const uint32_t* a, const uint32_t* b) {
    asm volatile(
        "mma.sync.aligned.m16n8k16.row.col.f32.f16.f16.f32 "
        "{%0,%1,%2,%3}, {%4,%5,%6,%7}, {%8,%9}, {%0,%1,%2,%3};"
        : "+f"(c[0]), "+f"(c[1]), "+f"(c[2]), "+f"(c[3])
        : "r"(a[0]), "r"(a[1]), "r"(a[2]), "r"(a[3]), "r"(b[0]), "r"(b[1]));
}

__device__ __forceinline__ void ldsm4(uint32_t* r, uint32_t addr) {
    asm volatile("ldmatrix.sync.aligned.m8n8.x4.shared.b16 {%0,%1,%2,%3}, [%4];"
        : "=r"(r[0]), "=r"(r[1]), "=r"(r[2]), "=r"(r[3]) : "r"(addr));
}

__device__ __forceinline__ void cpasync16(uint32_t dst, const void* src) {
    asm volatile("cp.async.cg.shared.global [%0], [%1], 16;" :: "r"(dst), "l"(src));
}
__device__ __forceinline__ void cp_commit() {
    asm volatile("cp.async.commit_group;");
}
template<int N>
__device__ __forceinline__ void cp_wait() {
    asm volatile("cp.async.wait_group %0;" :: "n"(N));
}

// ---------------- utility kernels ----------------
__global__ void zero_cnt_kernel() {
    if (threadIdx.x < NE) g_cnt[threadIdx.x] = 0;
}

__global__ void copy_kernel(const float* __restrict__ src, float* __restrict__ dst,
                            long long n4) {
    long long i = (long long)blockIdx.x * 256 + threadIdx.x;
    long long stride = (long long)gridDim.x * 256;
    for (; i < n4; i += stride)
        ((float4*)dst)[i] = ((const float4*)src)[i];
}

__global__ void conv_kernel(const float* __restrict__ in, h16* __restrict__ out,
                            long long total16) {
    long long idx = (long long)blockIdx.x * 256 + threadIdx.x;
    long long stride = (long long)gridDim.x * 256;
    for (; idx < total16; idx += stride) {
        const float4* ip = (const float4*)&in[idx * 16];
        float4 v0 = ip[0], v1 = ip[1], v2 = ip[2], v3 = ip[3];
        __half2 h[8];
        h[0] = __floats2half2_rn(v0.x, v0.y); h[1] = __floats2half2_rn(v0.z, v0.w);
        h[2] = __floats2half2_rn(v1.x, v1.y); h[3] = __floats2half2_rn(v1.z, v1.w);
        h[4] = __floats2half2_rn(v2.x, v2.y); h[5] = __floats2half2_rn(v2.z, v2.w);
        h[6] = __floats2half2_rn(v3.x, v3.y); h[7] = __floats2half2_rn(v3.z, v3.w);
        *(uint4*)&out[idx * 16]     = *(uint4*)&h[0];
        *(uint4*)&out[idx * 16 + 8] = *(uint4*)&h[4];
    }
}

__global__ void conv_interleave_kernel(const float* __restrict__ in, h16* __restrict__ out,
                                       int K, int I, int groups) {
    long long idx = (long long)blockIdx.x * 256 + threadIdx.x;
    int K16 = K >> 4;
    long long per_group = (long long)2 * I * K16;
    long long total = (long long)groups * per_group;
    if (idx >= total) return;
    int g = (int)(idx / per_group);
    long long rem = idx % per_group;
    int r = (int)(rem / K16);
    int kq = (int)(rem % K16) * 16;
    int outr = (r < I) ? (2 * r) : (2 * (r - I) + 1);
    const float4* ip = (const float4*)&in[((size_t)g * 2 * I + r) * K + kq];
    float4 v0 = ip[0], v1 = ip[1], v2 = ip[2], v3 = ip[3];
    __half2 h[8];
    h[0] = __floats2half2_rn(v0.x, v0.y); h[1] = __floats2half2_rn(v0.z, v0.w);
    h[2] = __floats2half2_rn(v1.x, v1.y); h[3] = __floats2half2_rn(v1.z, v1.w);
    h[4] = __floats2half2_rn(v2.x, v2.y); h[5] = __floats2half2_rn(v2.z, v2.w);
    h[6] = __floats2half2_rn(v3.x, v3.y); h[7] = __floats2half2_rn(v3.z, v3.w);
    h16* o = out + ((size_t)g * 2 * I + outr) * K + kq;
    *(uint4*)&o[0] = *(uint4*)&h[0];
    *(uint4*)&o[8] = *(uint4*)&h[4];
}

__global__ void rmsnorm_h_kernel(const float* __restrict__ x,
                                 const float* __restrict__ w,
                                 h16* __restrict__ o) {
    int t = blockIdx.x;
    float4 xv = ((const float4*)(x + (size_t)t * HH))[threadIdx.x];
    float s = xv.x * xv.x + xv.y * xv.y + xv.z * xv.z + xv.w * xv.w;
    __shared__ float red[256];
    red[threadIdx.x] = s;
    __syncthreads();
    for (int k = 128; k > 0; k >>= 1) {
        if (threadIdx.x < k) red[threadIdx.x] += red[threadIdx.x + k];
        __syncthreads();
    }
    float rs = rsqrtf(red[0] / (float)HH + EPSV);
    float4 wv = ((const float4*)w)[threadIdx.x];
    h16* op = o + (size_t)t * HH + threadIdx.x * 4;
    *(__half2*)&op[0] = __floats2half2_rn(xv.x * rs * wv.x, xv.y * rs * wv.y);
    *(__half2*)&op[2] = __floats2half2_rn(xv.z * rs * wv.z, xv.w * rs * wv.w);
}

__global__ void rmsnorm_fh_kernel(const float* __restrict__ x,
                                  const float* __restrict__ w,
                                  float* __restrict__ of, h16* __restrict__ oh) {
    int t = blockIdx.x;
    float4 xv = ((const float4*)(x + (size_t)t * HH))[threadIdx.x];
    float s = xv.x * xv.x + xv.y * xv.y + xv.z * xv.z + xv.w * xv.w;
    __shared__ float red[256];
    red[threadIdx.x] = s;
    __syncthreads();
    for (int k = 128; k > 0; k >>= 1) {
        if (threadIdx.x < k) red[threadIdx.x] += red[threadIdx.x + k];
        __syncthreads();
    }
    float rs = rsqrtf(red[0] / (float)HH + EPSV);
    float4 wv = ((const float4*)w)[threadIdx.x];
    float4 ov = make_float4(xv.x * rs * wv.x, xv.y * rs * wv.y, xv.z * rs * wv.z, xv.w * rs * wv.w);
    ((float4*)(of + (size_t)t * HH))[threadIdx.x] = ov;
    h16* op = oh + (size_t)t * HH + threadIdx.x * 4;
    *(__half2*)&op[0] = __floats2half2_rn(ov.x, ov.y);
    *(__half2*)&op[2] = __floats2half2_rn(ov.z, ov.w);
}

// rope in-place on fp16 qkv (fp32 math internally)
__global__ void rope_h_kernel(h16* __restrict__ qkv, const int* __restrict__ positions) {
    int idx = blockIdx.x * 256 + threadIdx.x;
    if (idx >= TT * (NHQ + NKVH) * 32) return;
    int t = idx / ((NHQ + NKVH) * 32);
    int rem = idx % ((NHQ + NKVH) * 32);
    int h = rem >> 5;
    int d = rem & 31;
    int off = (h < NHQ) ? h * HD : NHQ * HD + (h - NHQ) * HD;
    h16* p = qkv + (size_t)t * QKVD + off;
    float x1 = __half2float(p[d]);
    float x2 = __half2float(p[d + 32]);
    float pos = (float)positions[t];
    float invf = __expf(-0.2878231366f * (float)d);   // ln(10000)/32
    float fr = pos * invf;
    float c, s;
    __sincosf(fr, &s, &c);
    p[d]      = __float2half(x1 * c - x2 * s);
    p[d + 32] = __float2half(x2 * c + x1 * s);
}

// ---------------- flash attention: BR=128 x BC=64, fp16 input, register softmax ----------------
#define ATT_SMEM ((128 + 64 + 64) * 72 * 2)

__global__ __launch_bounds__(256) void attn_mma_kernel(
    const h16* __restrict__ qkv, h16* __restrict__ outH) {
    extern __shared__ char smraw[];
    h16* Qh = (h16*)smraw;
    h16* Kh = Qh + 128 * 72;
    h16* Vh = Kh + 64 * 72;

    int qblk = gridDim.x - 1 - blockIdx.x;
    int h = blockIdx.y;
    int kvh = h >> 2;
    int tid = threadIdx.x, lane = tid & 31, w = tid >> 5;
    int r = lane >> 2, tq = (lane & 3) * 2;
    int q0 = qblk * 128 + w * 16 + r;

    for (int i = tid; i < 128 * 8; i += 256) {
        int row = i >> 3, c = (i & 7) * 8;
        *(uint4*)&Qh[row * 72 + c] =
            *(const uint4*)&qkv[(size_t)(qblk * 128 + row) * QKVD + h * HD + c];
    }

    const float c2 = 0.18033688011112042f;
    float m0 = -1e30f, m1 = -1e30f, l0 = 0.f, l1 = 0.f;
    float oacc[8][4] = {};

    int ktmax = qblk * 2 + 1;
    for (int kt = 0; kt <= ktmax; kt++) {
        __syncthreads();
        for (int i = tid; i < 64 * 8; i += 256) {
            int row = i >> 3, c = (i & 7) * 8;
            size_t base = (size_t)(kt * 64 + row) * QKVD + NHQ * HD + kvh * HD;
            *(uint4*)&Kh[row * 72 + c] = *(const uint4*)&qkv[base + c];
            uint4 vv = *(const uint4*)&qkv[base + NKVH * HD + c];
            h16 tmp[8];
            *(uint4*)tmp = vv;
            #pragma unroll
            for (int j = 0; j < 8; j++)
                Vh[(c + j) * 72 + row] = tmp[j];
        }
        __syncthreads();

        float sacc[8][4] = {};
        #pragma unroll
        for (int kb = 0; kb < 4; kb++) {
            int kbo = kb * 16;
            uint32_t af[4];
            const h16* qb = Qh + (w * 16 + r) * 72 + kbo + tq;
            af[0] = *(const uint32_t*)qb;
            af[1] = *(const uint32_t*)(qb + 8 * 72);
            af[2] = *(const uint32_t*)(qb + 8);
            af[3] = *(const uint32_t*)(qb + 8 * 72 + 8);
            #pragma unroll
            for (int nn = 0; nn < 8; nn++) {
                uint32_t bf[2];
                const h16* kbp = Kh + (nn * 8 + r) * 72 + kbo + tq;
                bf[0] = *(const uint32_t*)kbp;
                bf[1] = *(const uint32_t*)(kbp + 8);
                mma16816(sacc[nn], af, bf);
            }
        }

        int colb = kt * 64;
        if ((colb + 63) > q0) {
            #pragma unroll
            for (int nn = 0; nn < 8; nn++) {
                int c0 = colb + nn * 8 + tq;
                sacc[nn][0] = (c0     <= q0    ) ? sacc[nn][0] * c2 : -1e30f;
                sacc[nn][1] = (c0 + 1 <= q0    ) ? sacc[nn][1] * c2 : -1e30f;
                sacc[nn][2] = (c0     <= q0 + 8) ? sacc[nn][2] * c2 : -1e30f;
                sacc[nn][3] = (c0 + 1 <= q0 + 8) ? sacc[nn][3] * c2 : -1e30f;
            }
        } else {
            #pragma unroll
            for (int nn = 0; nn < 8; nn++) {
                sacc[nn][0] *= c2; sacc[nn][1] *= c2;
                sacc[nn][2] *= c2; sacc[nn][3] *= c2;
            }
        }

        float mt0 = -1e30f, mt1 = -1e30f;
        #pragma unroll
        for (int nn = 0; nn < 8; nn++) {
            mt0 = fmaxf(mt0, fmaxf(sacc[nn][0], sacc[nn][1]));
            mt1 = fmaxf(mt1, fmaxf(sacc[nn][2], sacc[nn][3]));
        }
        mt0 = fmaxf(mt0, __shfl_xor_sync(0xffffffffu, mt0, 1));
        mt0 = fmaxf(mt0, __shfl_xor_sync(0xffffffffu, mt0, 2));
        mt1 = fmaxf(mt1, __shfl_xor_sync(0xffffffffu, mt1, 1));
        mt1 = fmaxf(mt1, __shfl_xor_sync(0xffffffffu, mt1, 2));
        float nm0 = fmaxf(m0, mt0), nm1 = fmaxf(m1, mt1);
        float corr0 = exp2f(m0 - nm0), corr1 = exp2f(m1 - nm1);
        m0 = nm0; m1 = nm1;

        uint32_t pa[8], pb[8];
        float s0 = 0.f, s1 = 0.f;
        #pragma unroll
        for (int nn = 0; nn < 8; nn++) {
            __half2 ta = __floats2half2_rn(sacc[nn][0] - nm0, sacc[nn][1] - nm0);
            __half2 tb = __floats2half2_rn(sacc[nn][2] - nm1, sacc[nn][3] - nm1);
            uint32_t ua, ub;
            asm("ex2.approx.f16x2 %0, %1;" : "=r"(ua) : "r"(*(uint32_t*)&ta));
            asm("ex2.approx.f16x2 %0, %1;" : "=r"(ub) : "r"(*(uint32_t*)&tb));
            pa[nn] = ua; pb[nn] = ub;
            float2 fa = __half22float2(*(__half2*)&ua);
            float2 fb = __half22float2(*(__half2*)&ub);
            s0 += fa.x + fa.y; s1 += fb.x + fb.y;
        }
        s0 += __shfl_xor_sync(0xffffffffu, s0, 1);
        s0 += __shfl_xor_sync(0xffffffffu, s0, 2);
        s1 += __shfl_xor_sync(0xffffffffu, s1, 1);
        s1 += __shfl_xor_sync(0xffffffffu, s1, 2);
        l0 = l0 * corr0 + s0;
        l1 = l1 * corr1 + s1;

        #pragma unroll
        for (int nn = 0; nn < 8; nn++) {
            oacc[nn][0] *= corr0; oacc[nn][1] *= corr0;
            oacc[nn][2] *= corr1; oacc[nn][3] *= corr1;
        }
        #pragma unroll
        for (int kb = 0; kb < 4; kb++) {
            uint32_t af[4] = { pa[2 * kb], pb[2 * kb], pa[2 * kb + 1], pb[2 * kb + 1] };
            int kbo = kb * 16;
            #pragma unroll
            for (int nn = 0; nn < 8; nn++) {
                uint32_t bf[2];
                const h16* vbp = Vh + (nn * 8 + r) * 72 + kbo + tq;
                bf[0] = *(const uint32_t*)vbp;
                bf[1] = *(const uint32_t*)(vbp + 8);
                mma16816(oacc[nn], af, bf);
            }
        }
    }

    float inv0 = 1.0f / l0, inv1 = 1.0f / l1;
    #pragma unroll
    for (int nn = 0; nn < 8; nn++) {
        int d0 = h * HD + nn * 8 + tq;
        *(__half2*)&outH[(size_t)q0 * HH + d0] =
            __floats2half2_rn(oacc[nn][0] * inv0, oacc[nn][1] * inv0);
        *(__half2*)&outH[(size_t)(q0 + 8) * HH + d0] =
            __floats2half2_rn(oacc[nn][2] * inv1, oacc[nn][3] * inv1);
    }
}

// ---------------- fp16 MMA GEMM, cp.async 3-stage pipeline, optional split-K ----------------
// MODE 0 + SPLITK==1: Cf = A*B^T (+Dadd, store)
// MODE 0 + SPLITK>1:  atomicAdd partial into Cf (pre-initialized)
// MODE 1: silu(g)*u pairs -> OutH (width halfW)
// MODE 2: atomicAdd(OutAtom[tok[row]*N+col] += wt[row]*val)
// MODE 3: plain fp16 store -> OutH (width N)
#define STG    3
#define SBUF   (128 * 40 * 2)
#define GEMM_SMEM (2 * STG * SBUF)

template<int MODE, bool AG, bool GR, int SPLITK>
__global__ __launch_bounds__(256) void gemm_kernel(
    const h16* __restrict__ Aall, const h16* __restrict__ Ball,
    float* __restrict__ Cf, const float* __restrict__ Dadd,
    h16* __restrict__ OutH, int halfW,
    float* __restrict__ OutAtom,
    int M0, int N, int K,
    long long Asl, long long Bsl, long long OslH) {

    int zz = blockIdx.z;
    int e  = GR ? (zz / SPLITK) : 0;
    int ks = GR ? (zz % SPLITK) : zz;
    int M = GR ? g_cnt[e] : M0;
    if ((int)blockIdx.y * 128 >= M) return;
    const int Keff = K / SPLITK;
    const int koff = ks * Keff;
    const h16* B = Ball + (size_t)e * Bsl;

    extern __shared__ __align__(16) h16 smg[];
    h16* As = smg;
    h16* Bs = smg + STG * 128 * 40;

    const int tid = threadIdx.x;
    const int lane = tid & 31;
    const int wid = tid >> 5;
    const int warp_m = (wid >> 2) * 64;
    const int warp_n = (wid & 3) * 32;
    const int row0 = blockIdx.y * 128;
    const int col0 = blockIdx.x * 128;

    const int lr = tid >> 1;
    const int lc = (tid & 1) * 16;
    int arow = row0 + lr; if (arow >= M) arow = M - 1;
    const h16* aptr;
    if (AG) {
        int t = g_tok[e * TT + arow];
        aptr = Aall + (size_t)t * K + koff + lc;
    } else {
        aptr = Aall + (size_t)e * Asl + (size_t)arow * K + koff + lc;
    }
    const h16* bptr = B + (size_t)(col0 + lr) * K + koff + lc;

    uint32_t asm_base = (uint32_t)__cvta_generic_to_shared(As);
    uint32_t bsm_base = (uint32_t)__cvta_generic_to_shared(Bs);
    uint32_t ast = asm_base + (uint32_t)(lr * 80 + lc * 2);
    uint32_t bst = bsm_base + (uint32_t)(lr * 80 + lc * 2);
    uint32_t aoff = asm_base + (uint32_t)((warp_m + (lane & 15)) * 80 + ((lane >> 4) << 4));
    uint32_t boff = bsm_base + (uint32_t)((warp_n + (lane & 7) + ((lane >> 4) << 3)) * 80
                                          + (((lane >> 3) & 1) << 4));

    const int nt = Keff >> 5;

    cpasync16(ast, aptr);            cpasync16(ast + 16, aptr + 8);
    cpasync16(bst, bptr);            cpasync16(bst + 16, bptr + 8);
    cp_commit();
    if (nt > 1) {
        cpasync16(ast + SBUF, aptr + 32);      cpasync16(ast + SBUF + 16, aptr + 40);
        cpasync16(bst + SBUF, bptr + 32);      cpasync16(bst + SBUF + 16, bptr + 40);
    }
    cp_commit();

    float acc[4][4][4] = {};
    const int r  = lane >> 2;
    const int tq = (lane & 3) * 2;
    int buf = 0, nxt = 2;
    for (int kt = 0; kt < nt; kt++) {
        cp_wait<1>();
        __syncthreads();
        if (kt + 2 < nt) {
            uint32_t so = (uint32_t)nxt * SBUF;
            const h16* ap = aptr + (kt + 2) * 32;
            const h16* bp = bptr + (kt + 2) * 32;
            cpasync16(ast + so, ap);       cpasync16(ast + so + 16, ap + 8);
            cpasync16(bst + so, bp);       cpasync16(bst + so + 16, bp + 8);
        }
        cp_commit();

        uint32_t abase = aoff + (uint32_t)buf * SBUF;
        uint32_t bbase = boff + (uint32_t)buf * SBUF;
        #pragma unroll
        for (int ksub = 0; ksub < 2; ksub++) {
            const uint32_t kbb = ksub * 32;
            uint32_t afr[4][4], bfr2[2][4];
            #pragma unroll
            for (int mt = 0; mt < 4; mt++)
                ldsm4(afr[mt], abase + mt * (16 * 80) + kbb);
            #pragma unroll
            for (int pr = 0; pr < 2; pr++)
                ldsm4(bfr2[pr], bbase + pr * (16 * 80) + kbb);
            #pragma unroll
            for (int mt = 0; mt < 4; mt++) {
                #pragma unroll
                for (int nn = 0; nn < 4; nn++) {
                    uint32_t bf[2] = { bfr2[nn >> 1][(nn & 1) * 2],
                                       bfr2[nn >> 1][(nn & 1) * 2 + 1] };
                    mma16816(acc[mt][nn], afr[mt], bf);
                }
            }
        }
        buf = (buf + 1 == STG) ? 0 : buf + 1;
        nxt = (nxt + 1 == STG) ? 0 : nxt + 1;
    }

    const int* tok = g_tok + e * TT;
    const float* wt = g_wt + e * TT;
    h16* outh = (MODE == 1) ? (OutH + (size_t)e * OslH) : OutH;

    #pragma unroll
    for (int mt = 0; mt < 4; mt++) {
        #pragma unroll
        for (int nn = 0; nn < 4; nn++) {
            int rr0 = row0 + warp_m + mt * 16 + r;
            int rr1 = rr0 + 8;
            int cc  = col0 + warp_n + nn * 8 + tq;
            if (MODE == 0 && SPLITK == 1) {
                if (rr0 < M) {
                    float2 v = make_float2(acc[mt][nn][0], acc[mt][nn][1]);
                    if (Dadd) { v.x += Dadd[(size_t)rr0 * N + cc]; v.y += Dadd[(size_t)rr0 * N + cc + 1]; }
                    *(float2*)&Cf[(size_t)rr0 * N + cc] = v;
                }
                if (rr1 < M) {
                    float2 v = make_float2(acc[mt][nn][2], acc[mt][nn][3]);
                    if (Dadd) { v.x += Dadd[(size_t)rr1 * N + cc]; v.y += Dadd[(size_t)rr1 * N + cc + 1]; }
                    *(float2*)&Cf[(size_t)rr1 * N + cc] = v;
                }
            } else if (MODE == 0) {
                if (rr0 < M) {
                    atomicAdd(&Cf[(size_t)rr0 * N + cc],     acc[mt][nn][0]);
                    atomicAdd(&Cf[(size_t)rr0 * N + cc + 1], acc[mt][nn][1]);
                }
                if (rr1 < M) {
                    atomicAdd(&Cf[(size_t)rr1 * N + cc],     acc[mt][nn][2]);
                    atomicAdd(&Cf[(size_t)rr1 * N + cc + 1], acc[mt][nn][3]);
                }
            } else if (MODE == 1) {
                int j = cc >> 1;
                if (rr0 < M) {
                    float g = acc[mt][nn][0], u = acc[mt][nn][1];
                    outh[(size_t)rr0 * halfW + j] = __float2half(g / (1.0f + __expf(-g)) * u);
                }
                if (rr1 < M) {
                    float g = acc[mt][nn][2], u = acc[mt][nn][3];
                    outh[(size_t)rr1 * halfW + j] = __float2half(g / (1.0f + __expf(-g)) * u);
                }
            } else if (MODE == 3) {
                if (rr0 < M)
                    *(__half2*)&OutH[(size_t)rr0 * N + cc] =
                        __floats2half2_rn(acc[mt][nn][0], acc[mt][nn][1]);
                if (rr1 < M)
                    *(__half2*)&OutH[(size_t)rr1 * N + cc] =
                        __floats2half2_rn(acc[mt][nn][2], acc[mt][nn][3]);
            } else {
                if (rr0 < M) {
                    int t = tok[rr0]; float w = wt[rr0];
                    atomicAdd(&OutAtom[(size_t)t * N + cc],     w * acc[mt][nn][0]);
                    atomicAdd(&OutAtom[(size_t)t * N + cc + 1], w * acc[mt][nn][1]);
                }
                if (rr1 < M) {
                    int t = tok[rr1]; float w = wt[rr1];
                    atomicAdd(&OutAtom[(size_t)t * N + cc],     w * acc[mt][nn][2]);
                    atomicAdd(&OutAtom[(size_t)t * N + cc + 1], w * acc[mt][nn][3]);
                }
            }
        }
    }
}

// ---------------- MoE routing ----------------
__global__ void gate_kernel(const float* __restrict__ m, const float* __restrict__ gw) {
    int t = blockIdx.x;
    __shared__ float logits[NE];
    int warp = threadIdx.x >> 5, lane = threadIdx.x & 31;
    const float* xr = m + (size_t)t * HH;
    const float* wr = gw + (size_t)warp * HH;
    float s = 0.0f;
    for (int i = lane; i < HH; i += 32) s += xr[i] * wr[i];
    for (int o = 16; o > 0; o >>= 1) s += __shfl_down_sync(0xffffffffu, s, o);
    if (lane == 0) logits[warp] = s;
    __syncthreads();
    if (threadIdx.x == 0) {
        float mx = logits[0];
        for (int e = 1; e < NE; e++) mx = fmaxf(mx, logits[e]);
        float p[NE]; float sum = 0.0f;
        for (int e = 0; e < NE; e++) { p[e] = __expf(logits[e] - mx); sum += p[e]; }
        for (int e = 0; e < NE; e++) p[e] /= sum;
        int i0 = 0;
        for (int e = 1; e < NE; e++) if (p[e] > p[i0]) i0 = e;
        int i1 = (i0 == 0) ? 1 : 0;
        for (int e = 0; e < NE; e++) if (e != i0 && p[e] > p[i1]) i1 = e;
        float inv = 1.0f / (p[i0] + p[i1]);
        int pos0 = atomicAdd(&g_cnt[i0], 1);
        g_tok[i0 * TT + pos0] = t; g_wt[i0 * TT + pos0] = p[i0] * inv;
        int pos1 = atomicAdd(&g_cnt[i1], 1);
        g_tok[i1 * TT + pos1] = t; g_wt[i1 * TT + pos1] = p[i1] * inv;
    }
}

// ---------------- launch ----------------
extern "C" void kernel_launch(void* const* d_in, const int* in_sizes, int n_in,
                              void* d_out, int out_size) {
    (void)in_sizes; (void)n_in; (void)out_size;
    const int*   positions = (const int*)  d_in[0];
    const float* hidden    = (const float*)d_in[1];
    const float* input_ln  = (const float*)d_in[2];
    const float* post_ln   = (const float*)d_in[3];
    const float* resid_ln  = (const float*)d_in[4];
    const float* qkv_w     = (const float*)d_in[5];
    const float* o_w       = (const float*)d_in[6];
    const float* gate_w    = (const float*)d_in[7];
    const float* ws        = (const float*)d_in[8];
    const float* w2s       = (const float*)d_in[9];
    const float* w13       = (const float*)d_in[10];
    const float* w2        = (const float*)d_in[11];
    float* out = (float*)d_out;

    float *p_resattn, *p_m;
    h16 *p_qkvh, *p_sh, *p_smh, *p_sattn, *p_ssilu, *p_sqkvw, *p_sow, *p_sw13i, *p_sw2, *p_swsi, *p_sw2s, *p_sact;
    cudaGetSymbolAddress((void**)&p_resattn, g_resattn);
    cudaGetSymbolAddress((void**)&p_m,       g_m);
    cudaGetSymbolAddress((void**)&p_qkvh,    s_qkvh);
    cudaGetSymbolAddress((void**)&p_sh,      s_h);
    cudaGetSymbolAddress((void**)&p_smh,     s_mh);
    cudaGetSymbolAddress((void**)&p_sattn,   s_attn);
    cudaGetSymbolAddress((void**)&p_ssilu,   s_silu);
    cudaGetSymbolAddress((void**)&p_sqkvw,   s_qkvw);
    cudaGetSymbolAddress((void**)&p_sow,     s_ow);
    cudaGetSymbolAddress((void**)&p_sw13i,   s_w13i);
    cudaGetSymbolAddress((void**)&p_sw2,     s_w2);
    cudaGetSymbolAddress((void**)&p_swsi,    s_wsi);
    cudaGetSymbolAddress((void**)&p_sw2s,    s_w2s);
    cudaGetSymbolAddress((void**)&p_sact,    s_act);

    static cudaStream_t sB = nullptr, sC = nullptr;
    static cudaEvent_t e0 = nullptr, eQkvw = nullptr, eConv = nullptr, eRes = nullptr,
                       eCpR = nullptr, eCp2 = nullptr, eMoE = nullptr;
    if (sB == nullptr) {
        cudaStreamCreateWithFlags(&sB, cudaStreamNonBlocking);
        cudaStreamCreateWithFlags(&sC, cudaStreamNonBlocking);
        cudaEventCreateWithFlags(&e0,    cudaEventDisableTiming);
        cudaEventCreateWithFlags(&eQkvw, cudaEventDisableTiming);
        cudaEventCreateWithFlags(&eConv, cudaEventDisableTiming);
        cudaEventCreateWithFlags(&eRes,  cudaEventDisableTiming);
        cudaEventCreateWithFlags(&eCpR,  cudaEventDisableTiming);
        cudaEventCreateWithFlags(&eCp2,  cudaEventDisableTiming);
        cudaEventCreateWithFlags(&eMoE,  cudaEventDisableTiming);
        cudaFuncSetAttribute(attn_mma_kernel, cudaFuncAttributeMaxDynamicSharedMemorySize, ATT_SMEM);
        cudaFuncSetAttribute((gemm_kernel<3, false, false, 1>), cudaFuncAttributeMaxDynamicSharedMemorySize, GEMM_SMEM);
        cudaFuncSetAttribute((gemm_kernel<0, false, false, 2>), cudaFuncAttributeMaxDynamicSharedMemorySize, GEMM_SMEM);
        cudaFuncSetAttribute((gemm_kernel<1, false, false, 1>), cudaFuncAttributeMaxDynamicSharedMemorySize, GEMM_SMEM);
        cudaFuncSetAttribute((gemm_kernel<1, true, true, 1>),   cudaFuncAttributeMaxDynamicSharedMemorySize, GEMM_SMEM);
        cudaFuncSetAttribute((gemm_kernel<2, false, true, 2>),  cudaFuncAttributeMaxDynamicSharedMemorySize, GEMM_SMEM);
    }

    // fork: stream B converts qkv_w FIRST, then the rest
    cudaEventRecord(e0, 0);
    cudaStreamWaitEvent(sB, e0, 0);
    conv_kernel<<<592, 256, 0, sB>>>(qkv_w, p_sqkvw, (long long)QKVD * HH / 16);
    cudaEventRecord(eQkvw, sB);
    conv_kernel<<<592, 256, 0, sB>>>(o_w, p_sow, (long long)HH * HH / 16);
    conv_interleave_kernel<<<(2 * HH * HH / 16 + 255) / 256, 256, 0, sB>>>(w13, p_sw13i, HH, HH, 1);
    conv_kernel<<<592, 256, 0, sB>>>(w2, p_sw2, (long long)HH * HH / 16);
    conv_interleave_kernel<<<((long long)NE * 2 * NI * HH / 16 + 255) / 256, 256, 0, sB>>>(ws, p_swsi, HH, NI, NE);
    conv_kernel<<<592, 256, 0, sB>>>(w2s, p_sw2s, (long long)NE * HH * NI / 16);
    cudaEventRecord(eConv, sB);

    // stream C: zero counters + pre-init resattn = hidden
    cudaStreamWaitEvent(sC, e0, 0);
    zero_cnt_kernel<<<1, 32, 0, sC>>>();
    copy_kernel<<<592, 256, 0, sC>>>(hidden, p_resattn, (long long)TT * HH / 4);
    cudaEventRecord(eCpR, sC);

    // main stream: rmsnorm concurrent with qkv conversion
    rmsnorm_h_kernel<<<TT, 256>>>(hidden, input_ln, p_sh);
    cudaStreamWaitEvent(0, eQkvw, 0);
    // qkv GEMM writes fp16 directly
    gemm_kernel<3, false, false, 1><<<dim3(QKVD / 128, TT / 128), 256, GEMM_SMEM>>>(
        p_sh, p_sqkvw, nullptr, nullptr, p_qkvh, 0, nullptr, TT, QKVD, HH, 0, 0, 0);
    rope_h_kernel<<<(TT * (NHQ + NKVH) * 32 + 255) / 256, 256>>>(p_qkvh, positions);
    attn_mma_kernel<<<dim3(TT / 128, NHQ), 256, ATT_SMEM>>>(p_qkvh, p_sattn);

    // o-proj: split-K=2, atomic accumulate into pre-initialized resattn
    cudaStreamWaitEvent(0, eConv, 0);
    cudaStreamWaitEvent(0, eCpR, 0);
    gemm_kernel<0, false, false, 2><<<dim3(HH / 128, TT / 128, 2), 256, GEMM_SMEM>>>(
        p_sattn, p_sow, p_resattn, nullptr, nullptr, 0, nullptr, TT, HH, HH, 0, 0, 0);
    cudaEventRecord(eRes, 0);

    // stream B: pre-init out = resattn (base for w2 + MoE atomics)
    cudaStreamWaitEvent(sB, eRes, 0);
    copy_kernel<<<592, 256, 0, sB>>>(p_resattn, out, (long long)TT * HH / 4);
    cudaEventRecord(eCp2, sB);

    // MoE branch on stream C
    cudaStreamWaitEvent(sC, eRes, 0);
    rmsnorm_fh_kernel<<<TT, 256, 0, sC>>>(p_resattn, post_ln, p_m, p_smh);
    gate_kernel<<<TT, 256, 0, sC>>>(p_m, gate_w);
    gemm_kernel<1, true, true, 1><<<dim3(2 * NI / 128, TT / 128, NE), 256, GEMM_SMEM, sC>>>(
        p_smh, p_swsi, nullptr, nullptr, p_sact, NI, nullptr,
        TT, 2 * NI, HH,
        0, (long long)2 * NI * HH, (long long)TT * NI);
    cudaStreamWaitEvent(sC, eCp2, 0);
    gemm_kernel<2, false, true, 2><<<dim3(HH / 128, TT / 128, NE * 2), 256, GEMM_SMEM, sC>>>(
        p_sact, p_sw2s, nullptr, nullptr, nullptr, 0, out,
        TT, HH, NI,
        (long long)TT * NI, (long long)HH * NI, 0);
    cudaEventRecord(eMoE, sC);

    // MLP branch on main stream: w2 split-K atomic into out (concurrent with moe2)
    rmsnorm_h_kernel<<<TT, 256>>>(p_resattn, resid_ln, p_sh);
    gemm_kernel<1, false, false, 1><<<dim3(2 * HH / 128, TT / 128), 256, GEMM_SMEM>>>(
        p_sh, p_sw13i, nullptr, nullptr, p_ssilu, HH, nullptr, TT, 2 * HH, HH, 0, 0, 0);
    cudaStreamWaitEvent(0, eCp2, 0);
    gemm_kernel<0, false, false, 2><<<dim3(HH / 128, TT / 128, 2), 256, GEMM_SMEM>>>(
        p_ssilu, p_sw2, out, nullptr, nullptr, 0, nullptr, TT, HH, HH, 0, 0, 0);

    // join
    cudaStreamWaitEvent(0, eMoE, 0);
}